// round 15
// baseline (speedup 1.0000x reference)
#include <cuda_runtime.h>
#include <math.h>
#include <stdint.h>

#define BB   4
#define N0   6000
#define HW   78
#define NPIX (HW*HW)        // 6084
#define ADDW (NPIX - N0)    // 84
#define NT   (NPIX + 1)     // 6085
#define NP   6144
#define PADT (NP - NT)      // 59
#define EMBD 512
#define NH   8
#define DH   64
#define ML   256
#define LWIN (NP/ML)        // 24
#define BH   (BB*NH)        // 32
#define NSPL 8              // a3 K-splits

// -------------------- scratch (device globals, no allocation) --------------------
__device__ float    d_h    [(size_t)BB*NT*EMBD];    // residual stream, layer 1
__device__ float    d_h2   [(size_t)BB*NT*EMBD];    // residual stream, layer 2 (ppeg output)
__device__ uint32_t d_xnh  [(size_t)BB*NP*256];     // ln output, bf16x2 packed
__device__ uint32_t d_qkvh [(size_t)BB*NP*768];     // qkv bf16x2: [token][pair]
__device__ uint32_t d_attnh[(size_t)BB*NP*256];     // attention out, bf16x2 packed
__device__ float    d_ql  [BH*ML*DH];
__device__ float    d_kl  [BH*ML*DH];
__device__ float    d_a2  [BH*ML*ML];
__device__ float    d_z0  [BH*ML*ML];
__device__ float    d_z1  [BH*ML*ML];
__device__ float    d_t0  [BH*ML*ML];
__device__ float    d_t1  [BH*ML*ML];
__device__ float    d_t2  [BH*ML*ML];
__device__ float    d_a3v [(size_t)NSPL*BH*ML*DH];  // per-split partial sums (no atomics)
__device__ float    d_w2  [BH*ML*DH];
__device__ float    d_rs  [(size_t)NSPL*BH*ML];     // per-split rowsum partials
__device__ float    d_mx  [2];
__device__ float    d_wct [49*EMBD];

__device__ __forceinline__ float dot64(const float* __restrict__ a, const float* __restrict__ kp) {
    float s = 0.f;
#pragma unroll
    for (int i = 0; i < 16; i++) {
        float4 x = *(const float4*)(kp + 4*i);
        s += a[4*i]*x.x + a[4*i+1]*x.y + a[4*i+2]*x.z + a[4*i+3]*x.w;
    }
    return s;
}

__device__ __forceinline__ uint32_t f2tf32(float f) {
    uint32_t r;
    asm("cvt.rna.tf32.f32 %0, %1;" : "=r"(r) : "f"(f));
    return r;
}

__device__ __forceinline__ uint32_t pkbf(float lo, float hi) {
    uint32_t r;
    asm("cvt.rn.bf16x2.f32 %0, %1, %2;" : "=r"(r) : "f"(hi), "f"(lo));
    return r;
}

__device__ __forceinline__ float blo(uint32_t w) { return __uint_as_float(w << 16); }
__device__ __forceinline__ float bhi(uint32_t w) { return __uint_as_float(w & 0xffff0000u); }

__device__ __forceinline__ uint32_t mulbf2(uint32_t a, uint32_t b) {
    uint32_t r;
    asm("mul.bf16x2 %0, %1, %2;" : "=r"(r) : "r"(a), "r"(b));
    return r;
}

__device__ __forceinline__ void mma_tf32(float* c, const uint32_t* a, const uint32_t* b) {
    asm volatile("mma.sync.aligned.m16n8k8.row.col.f32.tf32.tf32.f32 "
        "{%0,%1,%2,%3}, {%4,%5,%6,%7}, {%8,%9}, {%0,%1,%2,%3};"
        : "+f"(c[0]), "+f"(c[1]), "+f"(c[2]), "+f"(c[3])
        : "r"(a[0]), "r"(a[1]), "r"(a[2]), "r"(a[3]), "r"(b[0]), "r"(b[1]));
}

__device__ __forceinline__ void mma_bf16(float* c, const uint32_t* a, const uint32_t* b) {
    asm volatile("mma.sync.aligned.m16n8k16.row.col.f32.bf16.bf16.f32 "
        "{%0,%1,%2,%3}, {%4,%5,%6,%7}, {%8,%9}, {%0,%1,%2,%3};"
        : "+f"(c[0]), "+f"(c[1]), "+f"(c[2]), "+f"(c[3])
        : "r"(a[0]), "r"(a[1]), "r"(a[2]), "r"(a[3]), "r"(b[0]), "r"(b[1]));
}

// ==================== bf16 tensor-core GEMM, 128x128x16 double-buffered ====================
// act: 0 plain fp32 out, 1 relu fp32 out, 2 accumulate into C with PADT row shift,
//      4 bf16x2-packed output (C as uint32*, row stride N/2 words)
// aPacked: A is bf16x2-packed (uint32*, row stride K/2 words, sA in words)
__global__ __launch_bounds__(256) void bf16gemm_k(
    const float* __restrict__ A, const float* __restrict__ B,
    const float* __restrict__ bias, float* __restrict__ C,
    int M, int N, int K, size_t sA, size_t sC, int act, int aPacked)
{
    __shared__ uint32_t As[2][128][12];
    __shared__ uint32_t Bs[2][128][12];
    A += (size_t)blockIdx.z * sA;
    C += (size_t)blockIdx.z * sC;
    int bm = blockIdx.y * 128, bn = blockIdx.x * 128;
    int tid = threadIdx.x;
    int ar = tid >> 1, ak = (tid & 1) << 3;
    int aw = (tid & 1) << 2;
    int bn0 = (tid & 31) << 2, bkp = tid >> 5;
    int wid = tid >> 5, lane = tid & 31;
    int wy = wid >> 2, wx = wid & 3;
    int g = lane >> 2, tg = lane & 3;

    float acc[4][4][4];
#pragma unroll
    for (int mi = 0; mi < 4; mi++)
#pragma unroll
        for (int ni = 0; ni < 4; ni++)
#pragma unroll
            for (int q = 0; q < 4; q++) acc[mi][ni][q] = 0.f;

    int nk = K >> 4;

    {
        int r = bm + ar;
        if (aPacked) {
            uint4 wa = make_uint4(0u,0u,0u,0u);
            if (r < M) wa = *(const uint4*)((const uint32_t*)A + (size_t)r*(K>>1) + aw);
            As[0][ar][aw+0] = wa.x; As[0][ar][aw+1] = wa.y;
            As[0][ar][aw+2] = wa.z; As[0][ar][aw+3] = wa.w;
        } else {
            float4 a0 = make_float4(0.f,0.f,0.f,0.f), a1 = a0;
            if (r < M) {
                a0 = *(const float4*)(A + (size_t)r*K + ak);
                a1 = *(const float4*)(A + (size_t)r*K + ak + 4);
            }
            As[0][ar][aw+0] = pkbf(a0.x, a0.y);
            As[0][ar][aw+1] = pkbf(a0.z, a0.w);
            As[0][ar][aw+2] = pkbf(a1.x, a1.y);
            As[0][ar][aw+3] = pkbf(a1.z, a1.w);
        }
        float4 b0 = *(const float4*)(B + (size_t)(2*bkp  )*N + bn + bn0);
        float4 b1 = *(const float4*)(B + (size_t)(2*bkp+1)*N + bn + bn0);
        Bs[0][bn0+0][bkp] = pkbf(b0.x, b1.x);
        Bs[0][bn0+1][bkp] = pkbf(b0.y, b1.y);
        Bs[0][bn0+2][bkp] = pkbf(b0.z, b1.z);
        Bs[0][bn0+3][bkp] = pkbf(b0.w, b1.w);
    }
    __syncthreads();

    int buf = 0;
    for (int kt = 0; kt < nk; kt++) {
        float4 a0, a1, b0, b1;
        uint4 wa;
        bool pf = (kt + 1 < nk);
        if (pf) {
            int k0 = (kt + 1) << 4;
            int r = bm + ar;
            if (aPacked) {
                wa = make_uint4(0u,0u,0u,0u);
                if (r < M) wa = *(const uint4*)((const uint32_t*)A + (size_t)r*(K>>1) + (k0>>1) + aw);
            } else {
                a0 = make_float4(0.f,0.f,0.f,0.f); a1 = a0;
                if (r < M) {
                    a0 = *(const float4*)(A + (size_t)r*K + k0 + ak);
                    a1 = *(const float4*)(A + (size_t)r*K + k0 + ak + 4);
                }
            }
            b0 = *(const float4*)(B + (size_t)(k0 + 2*bkp  )*N + bn + bn0);
            b1 = *(const float4*)(B + (size_t)(k0 + 2*bkp+1)*N + bn + bn0);
        }
        uint32_t af[4][4];
#pragma unroll
        for (int mi = 0; mi < 4; mi++) {
            int r0 = wy*64 + mi*16;
            af[mi][0] = As[buf][r0 + g    ][tg];
            af[mi][1] = As[buf][r0 + g + 8][tg];
            af[mi][2] = As[buf][r0 + g    ][tg + 4];
            af[mi][3] = As[buf][r0 + g + 8][tg + 4];
        }
        uint32_t bfr[4][2];
#pragma unroll
        for (int ni = 0; ni < 4; ni++) {
            int c0 = wx*32 + ni*8;
            bfr[ni][0] = Bs[buf][c0 + g][tg];
            bfr[ni][1] = Bs[buf][c0 + g][tg + 4];
        }
#pragma unroll
        for (int mi = 0; mi < 4; mi++)
#pragma unroll
            for (int ni = 0; ni < 4; ni++)
                mma_bf16(acc[mi][ni], af[mi], bfr[ni]);

        if (pf) {
            int nb = buf ^ 1;
            if (aPacked) {
                As[nb][ar][aw+0] = wa.x; As[nb][ar][aw+1] = wa.y;
                As[nb][ar][aw+2] = wa.z; As[nb][ar][aw+3] = wa.w;
            } else {
                As[nb][ar][aw+0] = pkbf(a0.x, a0.y);
                As[nb][ar][aw+1] = pkbf(a0.z, a0.w);
                As[nb][ar][aw+2] = pkbf(a1.x, a1.y);
                As[nb][ar][aw+3] = pkbf(a1.z, a1.w);
            }
            Bs[nb][bn0+0][bkp] = pkbf(b0.x, b1.x);
            Bs[nb][bn0+1][bkp] = pkbf(b0.y, b1.y);
            Bs[nb][bn0+2][bkp] = pkbf(b0.z, b1.z);
            Bs[nb][bn0+3][bkp] = pkbf(b0.w, b1.w);
        }
        __syncthreads();
        buf ^= 1;
    }

#pragma unroll
    for (int mi = 0; mi < 4; mi++) {
#pragma unroll
        for (int half = 0; half < 2; half++) {
            int r = bm + wy*64 + mi*16 + g + half*8;
            if (r >= M) continue;
#pragma unroll
            for (int ni = 0; ni < 4; ni++) {
                int c = bn + wx*32 + ni*8 + 2*tg;
                float v0 = acc[mi][ni][half*2+0] + (bias ? bias[c]   : 0.f);
                float v1 = acc[mi][ni][half*2+1] + (bias ? bias[c+1] : 0.f);
                if (act == 1) { v0 = fmaxf(v0, 0.f); v1 = fmaxf(v1, 0.f); }
                if (act == 2) {
                    int rr = r - PADT;
                    if (rr >= 0) {
                        float2* p = (float2*)(C + (size_t)rr*N + c);
                        float2 cur = *p;
                        cur.x += v0; cur.y += v1;
                        *p = cur;
                    }
                } else if (act == 4) {
                    ((uint32_t*)C)[(size_t)r*(N >> 1) + (c >> 1)] = pkbf(v0, v1);
                } else {
                    *(float2*)(C + (size_t)r*N + c) = make_float2(v0, v1);
                }
            }
        }
    }
}

// ==================== tf32 tensor-core GEMM (pinv path), 128x128x8 ====================
__global__ __launch_bounds__(256) void tf32gemm_k(
    const float* __restrict__ A, const float* __restrict__ B,
    float* __restrict__ C, int Kd, size_t sAB,
    float cI, float eB, float sc)
{
    __shared__ uint32_t As[2][8][136];
    __shared__ uint32_t Bs[2][8][136];
    A += (size_t)blockIdx.z * sAB;
    B += (size_t)blockIdx.z * sAB;
    C += (size_t)blockIdx.z * sAB;
    const int N = 256;
    int bm = blockIdx.y * 128, bn = blockIdx.x * 128;
    int tid = threadIdx.x;
    int arow = tid >> 1, acol = (tid & 1) << 2;
    int brow = tid >> 5, bcol = (tid & 31) << 2;
    int wid = tid >> 5, lane = tid & 31;
    int wy = wid >> 2, wx = wid & 3;
    int g = lane >> 2, tg = lane & 3;

    float acc[4][4][4];
#pragma unroll
    for (int mi = 0; mi < 4; mi++)
#pragma unroll
        for (int ni = 0; ni < 4; ni++)
#pragma unroll
            for (int q = 0; q < 4; q++) acc[mi][ni][q] = 0.f;

    int nk = Kd >> 3;
    int col0 = bn + bcol;

    {
        float4 va = *(const float4*)(A + (size_t)(bm + arow)*Kd + acol);
        As[0][acol+0][arow] = f2tf32(va.x);
        As[0][acol+1][arow] = f2tf32(va.y);
        As[0][acol+2][arow] = f2tf32(va.z);
        As[0][acol+3][arow] = f2tf32(va.w);
        float4 vb = *(const float4*)(B + (size_t)brow*N + col0);
        float e0 = eB*vb.x, e1 = eB*vb.y, e2 = eB*vb.z, e3 = eB*vb.w;
        if (brow == col0    ) e0 += cI;
        if (brow == col0 + 1) e1 += cI;
        if (brow == col0 + 2) e2 += cI;
        if (brow == col0 + 3) e3 += cI;
        Bs[0][brow][bcol  ] = f2tf32(e0);
        Bs[0][brow][bcol+1] = f2tf32(e1);
        Bs[0][brow][bcol+2] = f2tf32(e2);
        Bs[0][brow][bcol+3] = f2tf32(e3);
    }
    __syncthreads();

    int buf = 0;
    for (int kt = 0; kt < nk; kt++) {
        float4 va, vb;
        bool pf = (kt + 1 < nk);
        if (pf) {
            int k0 = (kt + 1) << 3;
            va = *(const float4*)(A + (size_t)(bm + arow)*Kd + k0 + acol);
            vb = *(const float4*)(B + (size_t)(k0 + brow)*N + col0);
        }
        uint32_t af[4][4];
#pragma unroll
        for (int mi = 0; mi < 4; mi++) {
            int r0 = wy*64 + mi*16;
            af[mi][0] = As[buf][tg  ][r0 + g];
            af[mi][1] = As[buf][tg  ][r0 + g + 8];
            af[mi][2] = As[buf][tg+4][r0 + g];
            af[mi][3] = As[buf][tg+4][r0 + g + 8];
        }
        uint32_t bfr[4][2];
#pragma unroll
        for (int ni = 0; ni < 4; ni++) {
            int c0 = wx*32 + ni*8;
            bfr[ni][0] = Bs[buf][tg  ][c0 + g];
            bfr[ni][1] = Bs[buf][tg+4][c0 + g];
        }
#pragma unroll
        for (int mi = 0; mi < 4; mi++)
#pragma unroll
            for (int ni = 0; ni < 4; ni++)
                mma_tf32(acc[mi][ni], af[mi], bfr[ni]);

        if (pf) {
            int nb = buf ^ 1;
            int kr = ((kt + 1) << 3) + brow;
            As[nb][acol+0][arow] = f2tf32(va.x);
            As[nb][acol+1][arow] = f2tf32(va.y);
            As[nb][acol+2][arow] = f2tf32(va.z);
            As[nb][acol+3][arow] = f2tf32(va.w);
            float e0 = eB*vb.x, e1 = eB*vb.y, e2 = eB*vb.z, e3 = eB*vb.w;
            if (kr == col0    ) e0 += cI;
            if (kr == col0 + 1) e1 += cI;
            if (kr == col0 + 2) e2 += cI;
            if (kr == col0 + 3) e3 += cI;
            Bs[nb][brow][bcol  ] = f2tf32(e0);
            Bs[nb][brow][bcol+1] = f2tf32(e1);
            Bs[nb][brow][bcol+2] = f2tf32(e2);
            Bs[nb][brow][bcol+3] = f2tf32(e3);
        }
        __syncthreads();
        buf ^= 1;
    }

#pragma unroll
    for (int mi = 0; mi < 4; mi++) {
#pragma unroll
        for (int half = 0; half < 2; half++) {
            int r = bm + wy*64 + mi*16 + g + half*8;
#pragma unroll
            for (int ni = 0; ni < 4; ni++) {
                int c = bn + wx*32 + ni*8 + 2*tg;
                *(float2*)(C + (size_t)r*N + c) =
                    make_float2(sc*acc[mi][ni][half*2+0], sc*acc[mi][ni][half*2+1]);
            }
        }
    }
}

// ==================== fused attention (bf16), 64-wide chunks ====================
#define SW_QS 0
#define SW_KS 4608
#define SW_VS 6912
#define SW_PS 9216
#define SW_RS 13824
#define SM_FUSED_BYTES ((13824 + 4608 + 128)*4)

__global__ __launch_bounds__(256) void a3_fused_k() {
    extern __shared__ uint32_t sm[];
    uint32_t* qs = sm + SW_QS;
    uint32_t* Ks = sm + SW_KS;
    uint32_t* Vs = sm + SW_VS;
    uint32_t* Ps = sm + SW_PS;
    float* rsm = (float*)(sm + SW_RS);

    int split = blockIdx.x;
    int bm = blockIdx.y * 128;
    int z = blockIdx.z; int zb = z / NH, zh = z % NH;
    int tid = threadIdx.x;
    int wid = tid >> 5, lane = tid & 31;
    int wy = wid >> 2, wx = wid & 3;
    int wy2 = wid >> 1, wx2 = wid & 1;
    int g = lane >> 2, tg = lane & 3;

    if (tid < 128) rsm[tid] = 0.f;

    for (int i = tid; i < 128*16; i += 256) {
        int row = i >> 4, f4 = (i & 15) << 2;
        float4 v = *(const float4*)(d_ql + ((size_t)(z*ML + bm + row))*DH + f4);
        qs[row*36 + (f4>>1)    ] = pkbf(v.x, v.y);
        qs[row*36 + (f4>>1) + 1] = pkbf(v.z, v.w);
    }

    float acc_o[2][4][4];
#pragma unroll
    for (int a = 0; a < 2; a++)
#pragma unroll
        for (int b = 0; b < 4; b++)
#pragma unroll
            for (int q = 0; q < 4; q++) acc_o[a][b][q] = 0.f;
    float rs_loc[8];
#pragma unroll
    for (int a = 0; a < 8; a++) rs_loc[a] = 0.f;

    for (int ci = 0; ci < 12; ci++) {
        int c0 = split*768 + ci*64;
        for (int i = tid; i < 64*8; i += 256) {
            int tok = i >> 3, p4 = (i & 7) << 2;
            uint4 w = *(const uint4*)(d_qkvh + ((size_t)(zb*NP + c0 + tok))*768 + 256 + zh*32 + p4);
            Ks[tok*36 + p4+0] = w.x;
            Ks[tok*36 + p4+1] = w.y;
            Ks[tok*36 + p4+2] = w.z;
            Ks[tok*36 + p4+3] = w.w;
        }
        for (int i = tid; i < 32*8; i += 256) {
            int tp = i >> 3, p4 = (i & 7) << 2;
            const uint32_t* vb0 = d_qkvh + ((size_t)(zb*NP + c0 + 2*tp))*768 + 512 + zh*32 + p4;
            uint4 wa = *(const uint4*)vb0;
            uint4 wb = *(const uint4*)(vb0 + 768);
            Vs[(2*(p4+0)  )*36 + tp] = __byte_perm(wa.x, wb.x, 0x5410);
            Vs[(2*(p4+0)+1)*36 + tp] = __byte_perm(wa.x, wb.x, 0x7632);
            Vs[(2*(p4+1)  )*36 + tp] = __byte_perm(wa.y, wb.y, 0x5410);
            Vs[(2*(p4+1)+1)*36 + tp] = __byte_perm(wa.y, wb.y, 0x7632);
            Vs[(2*(p4+2)  )*36 + tp] = __byte_perm(wa.z, wb.z, 0x5410);
            Vs[(2*(p4+2)+1)*36 + tp] = __byte_perm(wa.z, wb.z, 0x7632);
            Vs[(2*(p4+3)  )*36 + tp] = __byte_perm(wa.w, wb.w, 0x5410);
            Vs[(2*(p4+3)+1)*36 + tp] = __byte_perm(wa.w, wb.w, 0x7632);
        }
        __syncthreads();

        float acc_s[4][2][4];
#pragma unroll
        for (int a = 0; a < 4; a++)
#pragma unroll
            for (int b = 0; b < 2; b++)
#pragma unroll
                for (int q = 0; q < 4; q++) acc_s[a][b][q] = 0.f;

#pragma unroll
        for (int kk = 0; kk < 4; kk++) {
            uint32_t af[4][4], bfr[2][2];
#pragma unroll
            for (int mi = 0; mi < 4; mi++) {
                int r0 = wy*64 + mi*16;
                af[mi][0] = qs[(r0 + g    )*36 + kk*8 + tg];
                af[mi][1] = qs[(r0 + g + 8)*36 + kk*8 + tg];
                af[mi][2] = qs[(r0 + g    )*36 + kk*8 + tg + 4];
                af[mi][3] = qs[(r0 + g + 8)*36 + kk*8 + tg + 4];
            }
#pragma unroll
            for (int ni = 0; ni < 2; ni++) {
                int cw = wx*16 + ni*8;
                bfr[ni][0] = Ks[(cw + g)*36 + kk*8 + tg];
                bfr[ni][1] = Ks[(cw + g)*36 + kk*8 + tg + 4];
            }
#pragma unroll
            for (int mi = 0; mi < 4; mi++)
#pragma unroll
                for (int ni = 0; ni < 2; ni++)
                    mma_bf16(acc_s[mi][ni], af[mi], bfr[ni]);
        }

#pragma unroll
        for (int mi = 0; mi < 4; mi++)
#pragma unroll
            for (int half = 0; half < 2; half++) {
                int rl = wy*64 + mi*16 + half*8 + g;
                float ra = 0.f;
#pragma unroll
                for (int ni = 0; ni < 2; ni++) {
                    int cp = wx*8 + ni*4 + tg;
                    float v0 = __expf(acc_s[mi][ni][half*2+0]);
                    float v1 = __expf(acc_s[mi][ni][half*2+1]);
                    Ps[rl*36 + cp] = pkbf(v0, v1);
                    ra += v0 + v1;
                }
                rs_loc[mi*2 + half] += ra;
            }
        __syncthreads();

#pragma unroll
        for (int kk = 0; kk < 4; kk++) {
            uint32_t af2[2][4], bf2[4][2];
#pragma unroll
            for (int mi2 = 0; mi2 < 2; mi2++) {
                int m0 = wy2*32 + mi2*16;
                af2[mi2][0] = Ps[(m0 + g    )*36 + kk*8 + tg];
                af2[mi2][1] = Ps[(m0 + g + 8)*36 + kk*8 + tg];
                af2[mi2][2] = Ps[(m0 + g    )*36 + kk*8 + tg + 4];
                af2[mi2][3] = Ps[(m0 + g + 8)*36 + kk*8 + tg + 4];
            }
#pragma unroll
            for (int ni2 = 0; ni2 < 4; ni2++) {
                int cw = wx2*32 + ni2*8;
                bf2[ni2][0] = Vs[(cw + g)*36 + kk*8 + tg];
                bf2[ni2][1] = Vs[(cw + g)*36 + kk*8 + tg + 4];
            }
#pragma unroll
            for (int mi2 = 0; mi2 < 2; mi2++)
#pragma unroll
                for (int ni2 = 0; ni2 < 4; ni2++)
                    mma_bf16(acc_o[mi2][ni2], af2[mi2], bf2[ni2]);
        }
        __syncthreads();
    }

#pragma unroll
    for (int j2 = 0; j2 < 8; j2++) {
        int rl = wy*64 + (j2>>1)*16 + (j2&1)*8 + g;
        atomicAdd(&rsm[rl], rs_loc[j2]);
    }
    __syncthreads();
    // plain stores into this split's private slab (no global atomics)
    if (tid < 128)
        d_rs[(size_t)split*BH*ML + (size_t)z*ML + bm + tid] = rsm[tid];
#pragma unroll
    for (int mi2 = 0; mi2 < 2; mi2++)
#pragma unroll
        for (int half = 0; half < 2; half++) {
            int m = wy2*32 + mi2*16 + half*8 + g;
#pragma unroll
            for (int ni2 = 0; ni2 < 4; ni2++) {
                int cc = wx2*32 + ni2*8 + 2*tg;
                float* dst = d_a3v + ((size_t)split*BH*ML + (size_t)z*ML + bm + m)*DH + cc;
                *(float2*)dst = make_float2(acc_o[mi2][ni2][half*2+0], acc_o[mi2][ni2][half*2+1]);
            }
        }
}

__global__ __launch_bounds__(256) void a1_fused_k() {
    extern __shared__ uint32_t sm[];
    uint32_t* qs = sm + SW_QS;
    uint32_t* Ks = sm + SW_KS;
    uint32_t* Vs = sm + SW_VS;
    uint32_t* Ps = sm + SW_PS;
    float* rsm = (float*)(sm + SW_RS);

    int bm = blockIdx.x * 128;
    int z = blockIdx.y; int zb = z / NH, zh = z % NH;
    int tid = threadIdx.x;
    int wid = tid >> 5, lane = tid & 31;
    int wy = wid >> 2, wx = wid & 3;
    int wy2 = wid >> 1, wx2 = wid & 1;
    int g = lane >> 2, tg = lane & 3;

    const uint32_t EIGHTH = 0x3E003E00u;

    if (tid < 128) rsm[tid] = 0.f;

    for (int i = tid; i < 128*8; i += 256) {
        int row = i >> 3, p4 = (i & 7) << 2;
        uint4 w = *(const uint4*)(d_qkvh + ((size_t)(zb*NP + bm + row))*768 + zh*32 + p4);
        qs[row*36 + p4+0] = mulbf2(w.x, EIGHTH);
        qs[row*36 + p4+1] = mulbf2(w.y, EIGHTH);
        qs[row*36 + p4+2] = mulbf2(w.z, EIGHTH);
        qs[row*36 + p4+3] = mulbf2(w.w, EIGHTH);
    }

    float acc_o[2][4][4];
#pragma unroll
    for (int a = 0; a < 2; a++)
#pragma unroll
        for (int b = 0; b < 4; b++)
#pragma unroll
            for (int q = 0; q < 4; q++) acc_o[a][b][q] = 0.f;
    float rs_loc[8];
#pragma unroll
    for (int a = 0; a < 8; a++) rs_loc[a] = 0.f;

    for (int lc = 0; lc < 4; lc++) {
        int base = lc*64;
        for (int i = tid; i < 64*16; i += 256) {
            int lm = i >> 4, f4 = (i & 15) << 2;
            float4 kv = *(const float4*)(d_kl + ((size_t)(z*ML + base + lm))*DH + f4);
            Ks[lm*36 + (f4>>1)    ] = pkbf(kv.x, kv.y);
            Ks[lm*36 + (f4>>1) + 1] = pkbf(kv.z, kv.w);
        }
        for (int i = tid; i < 32*16; i += 256) {
            int lp = i >> 4, f4 = (i & 15) << 2;
            const float* wb0 = d_w2 + ((size_t)(z*ML + base + 2*lp))*DH + f4;
            float4 w0 = *(const float4*)wb0;
            float4 w1 = *(const float4*)(wb0 + DH);
            Vs[(f4+0)*36 + lp] = pkbf(w0.x, w1.x);
            Vs[(f4+1)*36 + lp] = pkbf(w0.y, w1.y);
            Vs[(f4+2)*36 + lp] = pkbf(w0.z, w1.z);
            Vs[(f4+3)*36 + lp] = pkbf(w0.w, w1.w);
        }
        __syncthreads();

        float acc_s[4][2][4];
#pragma unroll
        for (int a = 0; a < 4; a++)
#pragma unroll
            for (int b = 0; b < 2; b++)
#pragma unroll
                for (int q = 0; q < 4; q++) acc_s[a][b][q] = 0.f;

#pragma unroll
        for (int kk = 0; kk < 4; kk++) {
            uint32_t af[4][4], bfr[2][2];
#pragma unroll
            for (int mi = 0; mi < 4; mi++) {
                int r0 = wy*64 + mi*16;
                af[mi][0] = qs[(r0 + g    )*36 + kk*8 + tg];
                af[mi][1] = qs[(r0 + g + 8)*36 + kk*8 + tg];
                af[mi][2] = qs[(r0 + g    )*36 + kk*8 + tg + 4];
                af[mi][3] = qs[(r0 + g + 8)*36 + kk*8 + tg + 4];
            }
#pragma unroll
            for (int ni = 0; ni < 2; ni++) {
                int cw = wx*16 + ni*8;
                bfr[ni][0] = Ks[(cw + g)*36 + kk*8 + tg];
                bfr[ni][1] = Ks[(cw + g)*36 + kk*8 + tg + 4];
            }
#pragma unroll
            for (int mi = 0; mi < 4; mi++)
#pragma unroll
                for (int ni = 0; ni < 2; ni++)
                    mma_bf16(acc_s[mi][ni], af[mi], bfr[ni]);
        }

#pragma unroll
        for (int mi = 0; mi < 4; mi++)
#pragma unroll
            for (int half = 0; half < 2; half++) {
                int rl = wy*64 + mi*16 + half*8 + g;
                float ra = 0.f;
#pragma unroll
                for (int ni = 0; ni < 2; ni++) {
                    int cp = wx*8 + ni*4 + tg;
                    float v0 = __expf(acc_s[mi][ni][half*2+0]);
                    float v1 = __expf(acc_s[mi][ni][half*2+1]);
                    Ps[rl*36 + cp] = pkbf(v0, v1);
                    ra += v0 + v1;
                }
                rs_loc[mi*2 + half] += ra;
            }
        __syncthreads();

#pragma unroll
        for (int kk = 0; kk < 4; kk++) {
            uint32_t af2[2][4], bf2[4][2];
#pragma unroll
            for (int mi2 = 0; mi2 < 2; mi2++) {
                int m0 = wy2*32 + mi2*16;
                af2[mi2][0] = Ps[(m0 + g    )*36 + kk*8 + tg];
                af2[mi2][1] = Ps[(m0 + g + 8)*36 + kk*8 + tg];
                af2[mi2][2] = Ps[(m0 + g    )*36 + kk*8 + tg + 4];
                af2[mi2][3] = Ps[(m0 + g + 8)*36 + kk*8 + tg + 4];
            }
#pragma unroll
            for (int ni2 = 0; ni2 < 4; ni2++) {
                int cw = wx2*32 + ni2*8;
                bf2[ni2][0] = Vs[(cw + g)*36 + kk*8 + tg];
                bf2[ni2][1] = Vs[(cw + g)*36 + kk*8 + tg + 4];
            }
#pragma unroll
            for (int mi2 = 0; mi2 < 2; mi2++)
#pragma unroll
                for (int ni2 = 0; ni2 < 4; ni2++)
                    mma_bf16(acc_o[mi2][ni2], af2[mi2], bf2[ni2]);
        }
        __syncthreads();
    }

#pragma unroll
    for (int j2 = 0; j2 < 8; j2++) {
        int rl = wy*64 + (j2>>1)*16 + (j2&1)*8 + g;
        atomicAdd(&rsm[rl], rs_loc[j2]);
    }
    __syncthreads();
#pragma unroll
    for (int mi2 = 0; mi2 < 2; mi2++)
#pragma unroll
        for (int half = 0; half < 2; half++) {
            int m = wy2*32 + mi2*16 + half*8 + g;
            float inv = 1.f / rsm[m];
#pragma unroll
            for (int ni2 = 0; ni2 < 4; ni2++) {
                int cc = wx2*32 + ni2*8 + 2*tg;
                d_attnh[(size_t)(zb*NP + bm + m)*256 + ((zh*64 + cc) >> 1)] =
                    pkbf(acc_o[mi2][ni2][half*2+0]*inv, acc_o[mi2][ni2][half*2+1]*inv);
            }
        }
}

// ==================== w2 = a2_inv @ (sum_s a3v[s] / sum_s rs[s]) ====================
// 64x64 tiles, K=256, batched over z. B operand reduced over NSPL slabs at load.
__global__ __launch_bounds__(256) void w2_gemm_k(
    const float* __restrict__ Ainv)
{
    __shared__ float As[16][64];
    __shared__ float Bs[16][64];
    const int Kd = 256, Nd = 64;
    int z = blockIdx.z;
    const float* A = Ainv + (size_t)z*ML*ML;
    float* C = d_w2 + (size_t)z*ML*DH;
    int bm = blockIdx.y * 64;
    int tid = threadIdx.x;
    int la_r = tid >> 2, la_c = (tid & 3) << 2;
    int lb_r = tid >> 4, lb_c = (tid & 15) << 2;
    int ty = tid >> 4, tx = tid & 15;
    float acc[4][4];
#pragma unroll
    for (int i = 0; i < 4; i++)
#pragma unroll
        for (int j = 0; j < 4; j++) acc[i][j] = 0.f;

    for (int k0 = 0; k0 < Kd; k0 += 16) {
        float4 av = *(const float4*)(A + (size_t)(bm + la_r)*Kd + k0 + la_c);
        As[la_c  ][la_r] = av.x;
        As[la_c+1][la_r] = av.y;
        As[la_c+2][la_r] = av.z;
        As[la_c+3][la_r] = av.w;
        int kr = k0 + lb_r;
        float4 bsum = make_float4(0.f,0.f,0.f,0.f);
        float rsum = 0.f;
#pragma unroll
        for (int s = 0; s < NSPL; s++) {
            float4 bv = *(const float4*)(d_a3v + ((size_t)s*BH*ML + (size_t)z*ML + kr)*DH + lb_c);
            bsum.x += bv.x; bsum.y += bv.y; bsum.z += bv.z; bsum.w += bv.w;
            rsum += d_rs[(size_t)s*BH*ML + (size_t)z*ML + kr];
        }
        float rsv = 1.f / rsum;
        Bs[lb_r][lb_c  ] = bsum.x * rsv;
        Bs[lb_r][lb_c+1] = bsum.y * rsv;
        Bs[lb_r][lb_c+2] = bsum.z * rsv;
        Bs[lb_r][lb_c+3] = bsum.w * rsv;
        __syncthreads();
#pragma unroll
        for (int kk = 0; kk < 16; kk++) {
            float a0 = As[kk][ty*4+0], a1 = As[kk][ty*4+1], a2 = As[kk][ty*4+2], a3 = As[kk][ty*4+3];
            float b0 = Bs[kk][tx*4+0], b1 = Bs[kk][tx*4+1], b2 = Bs[kk][tx*4+2], b3 = Bs[kk][tx*4+3];
            acc[0][0]+=a0*b0; acc[0][1]+=a0*b1; acc[0][2]+=a0*b2; acc[0][3]+=a0*b3;
            acc[1][0]+=a1*b0; acc[1][1]+=a1*b1; acc[1][2]+=a1*b2; acc[1][3]+=a1*b3;
            acc[2][0]+=a2*b0; acc[2][1]+=a2*b1; acc[2][2]+=a2*b2; acc[2][3]+=a2*b3;
            acc[3][0]+=a3*b0; acc[3][1]+=a3*b1; acc[3][2]+=a3*b2; acc[3][3]+=a3*b3;
        }
        __syncthreads();
    }
#pragma unroll
    for (int i = 0; i < 4; i++) {
        int r = bm + ty*4 + i;
#pragma unroll
        for (int j = 0; j < 4; j++) {
            int c = tx*4 + j;
            C[(size_t)r*Nd + c] = acc[i][j];
        }
    }
}

// -------------------- misc small kernels --------------------
__global__ void fill_cls_k(const float* __restrict__ cls) {
    int i = blockIdx.x*256 + threadIdx.x;
    if (i < BB*EMBD) d_h[(size_t)(i/EMBD)*NT*EMBD + (i % EMBD)] = cls[i % EMBD];
}

__global__ void fill_wrap_k() {
    int i = blockIdx.x*256 + threadIdx.x;
    if (i >= BB*ADDW*EMBD) return;
    int c = i % EMBD; int r = i / EMBD; int j = r % ADDW; int b = r / ADDW;
    d_h[((size_t)(b*NT + 1 + N0 + j))*EMBD + c] = d_h[((size_t)(b*NT + 1 + j))*EMBD + c];
}

// copy cls row from d_h into d_h2 (layer-2 residual buffer)
__global__ void copy_cls_k() {
    int i = blockIdx.x*256 + threadIdx.x;
    if (i >= BB*EMBD) return;
    int b = i / EMBD, c = i % EMBD;
    d_h2[(size_t)b*NT*EMBD + c] = d_h[(size_t)b*NT*EMBD + c];
}

// layernorm: one warp per row, shuffle reductions, bf16x2-packed output; residual source h
__global__ __launch_bounds__(256) void ln_pad_k2(const float* __restrict__ h,
                                                 const float* __restrict__ g, const float* __restrict__ bp) {
    int tid = threadIdx.x, wid = tid >> 5, lane = tid & 31;
    int row = blockIdx.x*8 + wid;
    int b = row / NP, t = row % NP;
    uint32_t* out = d_xnh + (size_t)row*256;
    if (t < PADT) {
#pragma unroll
        for (int k = 0; k < 4; k++)
            *(uint2*)(out + k*64 + lane*2) = make_uint2(0u, 0u);
        return;
    }
    const float* x = h + ((size_t)b*NT + (t - PADT))*EMBD;
    float4 v[4];
    float s = 0.f;
#pragma unroll
    for (int k = 0; k < 4; k++) {
        v[k] = *(const float4*)(x + k*128 + lane*4);
        s += v[k].x + v[k].y + v[k].z + v[k].w;
    }
#pragma unroll
    for (int o = 16; o > 0; o >>= 1) s += __shfl_xor_sync(0xffffffffu, s, o);
    float mean = s * (1.f/512.f);
    float s2 = 0.f;
#pragma unroll
    for (int k = 0; k < 4; k++) {
        v[k].x -= mean; v[k].y -= mean; v[k].z -= mean; v[k].w -= mean;
        s2 += v[k].x*v[k].x + v[k].y*v[k].y + v[k].z*v[k].z + v[k].w*v[k].w;
    }
#pragma unroll
    for (int o = 16; o > 0; o >>= 1) s2 += __shfl_xor_sync(0xffffffffu, s2, o);
    float inv = rsqrtf(s2 * (1.f/512.f) + 1e-5f);
#pragma unroll
    for (int k = 0; k < 4; k++) {
        float4 gv = *(const float4*)(g  + k*128 + lane*4);
        float4 bv = *(const float4*)(bp + k*128 + lane*4);
        uint2 o2;
        o2.x = pkbf(v[k].x*inv*gv.x + bv.x, v[k].y*inv*gv.y + bv.y);
        o2.y = pkbf(v[k].z*inv*gv.z + bv.z, v[k].w*inv*gv.w + bv.w);
        *(uint2*)(out + k*64 + lane*2) = o2;
    }
}

__global__ void landmarks_k() {
    int blk = blockIdx.x; int bh = blk >> 8; int i = blk & 255;
    int d = threadIdx.x;
    int b = bh / NH, h = bh % NH;
    int p = d >> 1, hi = d & 1;
    const uint32_t* base = d_qkvh + ((size_t)(b*NP) + (size_t)i*LWIN)*768 + h*32 + p;
    float sq = 0.f, sk = 0.f;
#pragma unroll
    for (int j = 0; j < LWIN; j++) {
        uint32_t wq = base[(size_t)j*768];
        uint32_t wk = base[(size_t)j*768 + 256];
        sq += hi ? bhi(wq) : blo(wq);
        sk += hi ? bhi(wk) : blo(wk);
    }
    d_ql[((size_t)(bh*ML + i))*DH + d] = sq * (0.125f / LWIN);
    d_kl[((size_t)(bh*ML + i))*DH + d] = sk * (1.f   / LWIN);
}

__global__ __launch_bounds__(256) void a2_k() {
    int blk = blockIdx.x; int bh = blk >> 8; int i = blk & 255;
    int tid = threadIdx.x;
    __shared__ float sq[64];
    __shared__ float red[256];
    if (tid < 64) sq[tid] = d_ql[((size_t)(bh*ML + i))*DH + tid];
    __syncthreads();
    float s = dot64(sq, d_kl + ((size_t)(bh*ML + tid))*DH);
    red[tid] = s; __syncthreads();
    for (int o = 128; o > 0; o >>= 1) { if (tid < o) red[tid] = fmaxf(red[tid], red[tid+o]); __syncthreads(); }
    float m = red[0]; __syncthreads();
    float p = expf(s - m);
    red[tid] = p; __syncthreads();
    for (int o = 128; o > 0; o >>= 1) { if (tid < o) red[tid] += red[tid+o]; __syncthreads(); }
    float Z = red[0];
    d_a2[((size_t)bh << 16) + ((size_t)i << 8) + tid] = p / Z;
}

__global__ void reset_mx_k() { d_mx[0] = 0.f; d_mx[1] = 0.f; }

__global__ __launch_bounds__(256) void a2_stats_k() {
    int bh = blockIdx.x; int tid = threadIdx.x;
    const float* a = d_a2 + ((size_t)bh << 16);
    float cs = 0.f;
    for (int i = 0; i < ML; i++) cs += a[(size_t)i*ML + tid];
    __shared__ float red[256];
    red[tid] = cs; __syncthreads();
    for (int o = 128; o > 0; o >>= 1) { if (tid < o) red[tid] = fmaxf(red[tid], red[tid+o]); __syncthreads(); }
    if (tid == 0) atomicMax((int*)&d_mx[1], __float_as_int(red[0]));
}

__global__ void z_init_k() {
    size_t idx = (size_t)blockIdx.x*256 + threadIdx.x;
    if (idx >= (size_t)BH*ML*ML) return;
    size_t bh = idx >> 16; size_t r = (idx >> 8) & 255; size_t c = idx & 255;
    float denom = d_mx[1];
    d_z0[idx] = d_a2[(bh << 16) + (c << 8) + r] / denom;
}

// conv residual: V bf16 in, RMW on packed bf16 attn
__global__ __launch_bounds__(256) void conv_res_k(const float* __restrict__ w) {
    __shared__ float vs[160*64];
    __shared__ float ws[33];
    int blk = blockIdx.x;
    int strip = blk % 48; int bh = blk / 48; int h = bh % NH; int b = bh / NH;
    int t0 = strip * 128;
    int tid = threadIdx.x;
    if (tid < 33) ws[tid] = w[h*33 + tid];
    for (int i = tid; i < 160*16; i += 256) {
        int row = i >> 4, f4 = (i & 15) << 2;
        int t = t0 - 16 + row;
        float4 v = make_float4(0.f,0.f,0.f,0.f);
        if (t >= 0 && t < NP) {
            uint2 wv = *(const uint2*)(d_qkvh + ((size_t)(b*NP + t))*768 + 512 + h*32 + (f4 >> 1));
            v.x = blo(wv.x); v.y = bhi(wv.x); v.z = blo(wv.y); v.w = bhi(wv.y);
        }
        *(float4*)(vs + row*64 + f4) = v;
    }
    __syncthreads();
#pragma unroll
    for (int j = 0; j < 8; j++) {
        int o = tid + j*256;
        int row = o >> 4, f4 = (o & 15) << 2;
        float4 s = make_float4(0.f,0.f,0.f,0.f);
#pragma unroll
        for (int k = 0; k < 33; k++) {
            float4 v = *(const float4*)(vs + (row + k)*64 + f4);
            float wk = ws[k];
            s.x += v.x*wk; s.y += v.y*wk; s.z += v.z*wk; s.w += v.w*wk;
        }
        uint2* dst = (uint2*)(d_attnh + (size_t)(b*NP + t0 + row)*256 + ((h*64 + f4) >> 1));
        uint2 cur = *dst;
        cur.x = pkbf(blo(cur.x) + s.x, bhi(cur.x) + s.y);
        cur.y = pkbf(blo(cur.y) + s.z, bhi(cur.y) + s.w);
        *dst = cur;
    }
}

// combined PPEG weights
__global__ void wtrans_k(const float* __restrict__ w7, const float* __restrict__ w5,
                         const float* __restrict__ w3) {
    int i = blockIdx.x*256 + threadIdx.x;
    if (i >= 49*EMBD) return;
    int aq = i / EMBD, c = i % EMBD;
    int a = aq / 7, q = aq % 7;
    float v = w7[c*49 + aq];
    if (a >= 1 && a <= 5 && q >= 1 && q <= 5) v += w5[c*25 + (a-1)*5 + (q-1)];
    if (a >= 2 && a <= 4 && q >= 2 && q <= 4) v += w3[c*9  + (a-2)*3 + (q-2)];
    d_wct[i] = v;
}

// PPEG: row-tiled single 7x7 conv, reads d_h, writes DIRECTLY into d_h2 token rows
#define PP_SMEM_BYTES (7*84*32*4)
__global__ __launch_bounds__(256) void ppeg3_k(
    const float* __restrict__ b7, const float* __restrict__ b5, const float* __restrict__ b3)
{
    extern __shared__ float sb[];
    int cg = blockIdx.x;
    int i  = blockIdx.y;
    int b  = blockIdx.z;
    int tid = threadIdx.x;
    const float* hbase = d_h + ((size_t)(b*NT + 1))*EMBD + cg*32;
    for (int idx = tid; idx < 7*84*8; idx += 256) {
        int f4 = (idx & 7) << 2;
        int jj = (idx >> 3) % 84;
        int r  = idx / (84*8);
        int ii = i - 3 + r, px = jj - 3;
        float4 v = make_float4(0.f,0.f,0.f,0.f);
        if (ii >= 0 && ii < HW && px >= 0 && px < HW)
            v = *(const float4*)(hbase + (size_t)(ii*HW + px)*EMBD + f4);
        *(float4*)(sb + (r*84 + jj)*32 + f4) = v;
    }
    __syncthreads();
    int c = tid & 31, jgrp = tid >> 5;
    float wr[49];
#pragma unroll
    for (int t = 0; t < 49; t++) wr[t] = d_wct[t*EMBD + cg*32 + c];
    float bs = b7[cg*32 + c] + b5[cg*32 + c] + b3[cg*32 + c];
    for (int j = jgrp; j < HW; j += 8) {
        float s = sb[(3*84 + j + 3)*32 + c] + bs;
#pragma unroll
        for (int a = 0; a < 7; a++)
#pragma unroll
            for (int q = 0; q < 7; q++)
                s += sb[(a*84 + j + q)*32 + c] * wr[a*7 + q];
        d_h2[((size_t)(b*NT + 1) + i*HW + j)*EMBD + cg*32 + c] = s;
    }
}

__global__ __launch_bounds__(256) void head_k(
    const float* __restrict__ h,
    const float* __restrict__ g, const float* __restrict__ bp,
    const float* __restrict__ w, const float* __restrict__ bias, float* __restrict__ out)
{
    int b = blockIdx.x; int tid = threadIdx.x;
    __shared__ float xs[512];
    __shared__ float red[256];
    __shared__ float lg[4];
    const float* x = h + (size_t)b*NT*EMBD;
    float v0 = x[tid], v1 = x[tid+256];
    red[tid] = v0 + v1; __syncthreads();
    for (int o = 128; o > 0; o >>= 1) { if (tid < o) red[tid] += red[tid+o]; __syncthreads(); }
    float mean = red[0] * (1.f/512.f); __syncthreads();
    float e0 = v0 - mean, e1 = v1 - mean;
    red[tid] = e0*e0 + e1*e1; __syncthreads();
    for (int o = 128; o > 0; o >>= 1) { if (tid < o) red[tid] += red[tid+o]; __syncthreads(); }
    float inv = rsqrtf(red[0] * (1.f/512.f) + 1e-5f);
    xs[tid]     = e0*inv*g[tid]     + bp[tid];
    xs[tid+256] = e1*inv*g[tid+256] + bp[tid+256];
    __syncthreads();
    if (tid < 4) {
        float s = bias[tid];
        for (int k = 0; k < 512; k++) s += xs[k]*w[k*4 + tid];
        lg[tid] = s;
    }
    __syncthreads();
    if (tid == 0) {
        int best = 0; float bv = lg[0];
        for (int k = 1; k < 4; k++) if (lg[k] > bv) { bv = lg[k]; best = k; }
        float S = 1.f;
        for (int k = 0; k < 4; k++) {
            float hz = 1.f / (1.f + expf(-lg[k]));
            out[b*4 + k] = hz;
            S *= (1.f - hz);
            out[16 + b*4 + k] = S;
        }
        out[32 + b] = (float)best;
    }
}

// -------------------- host orchestration --------------------
static float* symaddr(const void* sym) { void* p = nullptr; cudaGetSymbolAddress(&p, sym); return (float*)p; }

static void attn_layer(float* hbuf,
                       const float* lng, const float* lnb, const float* qkvw,
                       const float* outw, const float* outb, const float* resw)
{
    float* xnhp  = symaddr(d_xnh);
    float* qkvp  = symaddr(d_qkvh);
    float* attnp = symaddr(d_attnh);
    float* a2p   = symaddr(d_a2);
    float* z0p   = symaddr(d_z0);
    float* z1p   = symaddr(d_z1);
    float* t0p   = symaddr(d_t0);
    float* t1p   = symaddr(d_t1);
    float* t2p   = symaddr(d_t2);

    ln_pad_k2<<<BB*NP/8, 256>>>(hbuf, lng, lnb);
    bf16gemm_k<<<dim3(1536/128, NP/128, BB), 256>>>(
        xnhp, qkvw, nullptr, qkvp, NP, 1536, EMBD,
        (size_t)NP*256, (size_t)NP*768, 4, 1);
    landmarks_k<<<BH*ML, 64>>>();
    a2_k<<<BH*ML, 256>>>();
    reset_mx_k<<<1, 1>>>();
    a2_stats_k<<<BH, 256>>>();
    z_init_k<<<(BH*ML*ML + 255)/256, 256>>>();

    const size_t SB = (size_t)ML*ML;
    float* zin = z0p; float* zout = z1p;
    for (int it = 0; it < 6; it++) {
        tf32gemm_k<<<dim3(2, 2, BH), 256>>>(a2p, zin, t0p, 256, SB, 0.f,  1.f, 1.f);
        tf32gemm_k<<<dim3(2, 2, BH), 256>>>(t0p, t0p, t1p, 256, SB, 7.f, -1.f, 1.f);
        tf32gemm_k<<<dim3(2, 2, BH), 256>>>(t0p, t1p, t2p, 256, SB, 15.f,-1.f, 1.f);
        tf32gemm_k<<<dim3(2, 2, BH), 256>>>(zin, t2p, zout,256, SB, 13.f,-1.f, 0.25f);
        float* tmp = zin; zin = zout; zout = tmp;
    }
    // zin holds a2_inv (d_z0)

    a3_fused_k<<<dim3(NSPL, 2, BH), 256, SM_FUSED_BYTES>>>();
    w2_gemm_k<<<dim3(1, 4, BH), 256>>>(zin);
    a1_fused_k<<<dim3(NP/128, BH), 256, SM_FUSED_BYTES>>>();

    conv_res_k<<<BB*NH*48, 256>>>(resw);
    // out projection: A packed (d_attnh), accumulate into residual buffer (act=2)
    bf16gemm_k<<<dim3(EMBD/128, NP/128, BB), 256>>>(
        attnp, outw, outb, hbuf, NP, EMBD, EMBD,
        (size_t)NP*256, (size_t)NT*EMBD, 2, 1);
}

extern "C" void kernel_launch(void* const* d_in, const int* in_sizes, int n_in,
                              void* d_out, int out_size)
{
    (void)in_sizes; (void)n_in; (void)out_size;
    const float* x_path = (const float*)d_in[0];
    const float* fc1_w  = (const float*)d_in[1];
    const float* fc1_b  = (const float*)d_in[2];
    const float* cls    = (const float*)d_in[3];
    const float* ln1g   = (const float*)d_in[4];
    const float* ln1b   = (const float*)d_in[5];
    const float* qkv1w  = (const float*)d_in[6];
    const float* out1w  = (const float*)d_in[7];
    const float* out1b  = (const float*)d_in[8];
    const float* res1w  = (const float*)d_in[9];
    const float* ln2g   = (const float*)d_in[10];
    const float* ln2b   = (const float*)d_in[11];
    const float* qkv2w  = (const float*)d_in[12];
    const float* out2w  = (const float*)d_in[13];
    const float* out2b  = (const float*)d_in[14];
    const float* res2w  = (const float*)d_in[15];
    const float* c7w    = (const float*)d_in[16];
    const float* c7b    = (const float*)d_in[17];
    const float* c5w    = (const float*)d_in[18];
    const float* c5b    = (const float*)d_in[19];
    const float* c3w    = (const float*)d_in[20];
    const float* c3b    = (const float*)d_in[21];
    const float* ng     = (const float*)d_in[22];
    const float* nb     = (const float*)d_in[23];
    const float* fc2w   = (const float*)d_in[24];
    const float* fc2b   = (const float*)d_in[25];
    float* out = (float*)d_out;

    static int cfg = 0;
    if (!cfg) {
        cudaFuncSetAttribute(a3_fused_k, cudaFuncAttributeMaxDynamicSharedMemorySize, SM_FUSED_BYTES);
        cudaFuncSetAttribute(a1_fused_k, cudaFuncAttributeMaxDynamicSharedMemorySize, SM_FUSED_BYTES);
        cudaFuncSetAttribute(ppeg3_k,    cudaFuncAttributeMaxDynamicSharedMemorySize, PP_SMEM_BYTES);
        cfg = 1;
    }

    float* hp  = symaddr(d_h);
    float* h2p = symaddr(d_h2);

    bf16gemm_k<<<dim3(EMBD/128, (N0 + 127)/128, BB), 256>>>(
        x_path, fc1_w, fc1_b, hp + EMBD, N0, EMBD, 1024,
        (size_t)N0*1024, (size_t)NT*EMBD, 1, 0);
    fill_cls_k<<<(BB*EMBD + 255)/256, 256>>>(cls);
    fill_wrap_k<<<(BB*ADDW*EMBD + 255)/256, 256>>>();
    wtrans_k<<<(49*EMBD + 255)/256, 256>>>(c7w, c5w, c3w);

    attn_layer(hp, ln1g, ln1b, qkv1w, out1w, out1b, res1w);

    ppeg3_k<<<dim3(16, HW, BB), 256, PP_SMEM_BYTES>>>(c7b, c5b, c3b);
    copy_cls_k<<<(BB*EMBD + 255)/256, 256>>>();

    attn_layer(h2p, ln2g, ln2b, qkv2w, out2w, out2b, res2w);

    head_k<<<BB, 256>>>(h2p, ng, nb, fc2w, fc2b, out);
}

// round 16
// speedup vs baseline: 1.0069x; 1.0069x over previous
#include <cuda_runtime.h>
#include <math.h>
#include <stdint.h>

#define BB   4
#define N0   6000
#define HW   78
#define NPIX (HW*HW)        // 6084
#define ADDW (NPIX - N0)    // 84
#define NT   (NPIX + 1)     // 6085
#define NP   6144
#define PADT (NP - NT)      // 59
#define EMBD 512
#define NH   8
#define DH   64
#define ML   256
#define LWIN (NP/ML)        // 24
#define BH   (BB*NH)        // 32

// -------------------- scratch (device globals, no allocation) --------------------
__device__ float    d_h    [(size_t)BB*NT*EMBD];    // residual stream, layer 1
__device__ float    d_h2   [(size_t)BB*NT*EMBD];    // residual stream, layer 2 (ppeg output)
__device__ uint32_t d_xnh  [(size_t)BB*NP*256];     // ln output, bf16x2 packed
__device__ uint32_t d_qkvh [(size_t)BB*NP*768];     // qkv bf16x2: [token][pair]
__device__ uint32_t d_attnh[(size_t)BB*NP*256];     // attention out, bf16x2 packed
__device__ float    d_ql  [BH*ML*DH];
__device__ float    d_kl  [BH*ML*DH];
__device__ float    d_a2  [BH*ML*ML];
__device__ float    d_z0  [BH*ML*ML];
__device__ float    d_z1  [BH*ML*ML];
__device__ float    d_t0  [BH*ML*ML];
__device__ float    d_t1  [BH*ML*ML];
__device__ float    d_t2  [BH*ML*ML];
__device__ float    d_a3v [BH*ML*DH];
__device__ float    d_w2  [BH*ML*DH];
__device__ float    d_rs  [BH*ML];
__device__ float    d_mxb [BH];                     // per-(b,h) col-sum max (plain stores)
__device__ float    d_wct [49*EMBD];

__device__ __forceinline__ float dot64(const float* __restrict__ a, const float* __restrict__ kp) {
    float s = 0.f;
#pragma unroll
    for (int i = 0; i < 16; i++) {
        float4 x = *(const float4*)(kp + 4*i);
        s += a[4*i]*x.x + a[4*i+1]*x.y + a[4*i+2]*x.z + a[4*i+3]*x.w;
    }
    return s;
}

__device__ __forceinline__ uint32_t f2tf32(float f) {
    uint32_t r;
    asm("cvt.rna.tf32.f32 %0, %1;" : "=r"(r) : "f"(f));
    return r;
}

__device__ __forceinline__ uint32_t pkbf(float lo, float hi) {
    uint32_t r;
    asm("cvt.rn.bf16x2.f32 %0, %1, %2;" : "=r"(r) : "f"(hi), "f"(lo));
    return r;
}

__device__ __forceinline__ float blo(uint32_t w) { return __uint_as_float(w << 16); }
__device__ __forceinline__ float bhi(uint32_t w) { return __uint_as_float(w & 0xffff0000u); }

__device__ __forceinline__ uint32_t mulbf2(uint32_t a, uint32_t b) {
    uint32_t r;
    asm("mul.bf16x2 %0, %1, %2;" : "=r"(r) : "r"(a), "r"(b));
    return r;
}

__device__ __forceinline__ void mma_tf32(float* c, const uint32_t* a, const uint32_t* b) {
    asm volatile("mma.sync.aligned.m16n8k8.row.col.f32.tf32.tf32.f32 "
        "{%0,%1,%2,%3}, {%4,%5,%6,%7}, {%8,%9}, {%0,%1,%2,%3};"
        : "+f"(c[0]), "+f"(c[1]), "+f"(c[2]), "+f"(c[3])
        : "r"(a[0]), "r"(a[1]), "r"(a[2]), "r"(a[3]), "r"(b[0]), "r"(b[1]));
}

__device__ __forceinline__ void mma_bf16(float* c, const uint32_t* a, const uint32_t* b) {
    asm volatile("mma.sync.aligned.m16n8k16.row.col.f32.bf16.bf16.f32 "
        "{%0,%1,%2,%3}, {%4,%5,%6,%7}, {%8,%9}, {%0,%1,%2,%3};"
        : "+f"(c[0]), "+f"(c[1]), "+f"(c[2]), "+f"(c[3])
        : "r"(a[0]), "r"(a[1]), "r"(a[2]), "r"(a[3]), "r"(b[0]), "r"(b[1]));
}

// ==================== bf16 tensor-core GEMM, 128x128x16 double-buffered ====================
// act: 0 plain fp32 out, 1 relu fp32 out, 2 accumulate into C with PADT row shift,
//      4 bf16x2-packed output (C as uint32*, row stride N/2 words)
// aPacked: A is bf16x2-packed (uint32*, row stride K/2 words, sA in words)
__global__ __launch_bounds__(256) void bf16gemm_k(
    const float* __restrict__ A, const float* __restrict__ B,
    const float* __restrict__ bias, float* __restrict__ C,
    int M, int N, int K, size_t sA, size_t sC, int act, int aPacked)
{
    __shared__ uint32_t As[2][128][12];
    __shared__ uint32_t Bs[2][128][12];
    A += (size_t)blockIdx.z * sA;
    C += (size_t)blockIdx.z * sC;
    int bm = blockIdx.y * 128, bn = blockIdx.x * 128;
    int tid = threadIdx.x;
    int ar = tid >> 1, ak = (tid & 1) << 3;
    int aw = (tid & 1) << 2;
    int bn0 = (tid & 31) << 2, bkp = tid >> 5;
    int wid = tid >> 5, lane = tid & 31;
    int wy = wid >> 2, wx = wid & 3;
    int g = lane >> 2, tg = lane & 3;

    float acc[4][4][4];
#pragma unroll
    for (int mi = 0; mi < 4; mi++)
#pragma unroll
        for (int ni = 0; ni < 4; ni++)
#pragma unroll
            for (int q = 0; q < 4; q++) acc[mi][ni][q] = 0.f;

    int nk = K >> 4;

    {
        int r = bm + ar;
        if (aPacked) {
            uint4 wa = make_uint4(0u,0u,0u,0u);
            if (r < M) wa = *(const uint4*)((const uint32_t*)A + (size_t)r*(K>>1) + aw);
            As[0][ar][aw+0] = wa.x; As[0][ar][aw+1] = wa.y;
            As[0][ar][aw+2] = wa.z; As[0][ar][aw+3] = wa.w;
        } else {
            float4 a0 = make_float4(0.f,0.f,0.f,0.f), a1 = a0;
            if (r < M) {
                a0 = *(const float4*)(A + (size_t)r*K + ak);
                a1 = *(const float4*)(A + (size_t)r*K + ak + 4);
            }
            As[0][ar][aw+0] = pkbf(a0.x, a0.y);
            As[0][ar][aw+1] = pkbf(a0.z, a0.w);
            As[0][ar][aw+2] = pkbf(a1.x, a1.y);
            As[0][ar][aw+3] = pkbf(a1.z, a1.w);
        }
        float4 b0 = *(const float4*)(B + (size_t)(2*bkp  )*N + bn + bn0);
        float4 b1 = *(const float4*)(B + (size_t)(2*bkp+1)*N + bn + bn0);
        Bs[0][bn0+0][bkp] = pkbf(b0.x, b1.x);
        Bs[0][bn0+1][bkp] = pkbf(b0.y, b1.y);
        Bs[0][bn0+2][bkp] = pkbf(b0.z, b1.z);
        Bs[0][bn0+3][bkp] = pkbf(b0.w, b1.w);
    }
    __syncthreads();

    int buf = 0;
    for (int kt = 0; kt < nk; kt++) {
        float4 a0, a1, b0, b1;
        uint4 wa;
        bool pf = (kt + 1 < nk);
        if (pf) {
            int k0 = (kt + 1) << 4;
            int r = bm + ar;
            if (aPacked) {
                wa = make_uint4(0u,0u,0u,0u);
                if (r < M) wa = *(const uint4*)((const uint32_t*)A + (size_t)r*(K>>1) + (k0>>1) + aw);
            } else {
                a0 = make_float4(0.f,0.f,0.f,0.f); a1 = a0;
                if (r < M) {
                    a0 = *(const float4*)(A + (size_t)r*K + k0 + ak);
                    a1 = *(const float4*)(A + (size_t)r*K + k0 + ak + 4);
                }
            }
            b0 = *(const float4*)(B + (size_t)(k0 + 2*bkp  )*N + bn + bn0);
            b1 = *(const float4*)(B + (size_t)(k0 + 2*bkp+1)*N + bn + bn0);
        }
        uint32_t af[4][4];
#pragma unroll
        for (int mi = 0; mi < 4; mi++) {
            int r0 = wy*64 + mi*16;
            af[mi][0] = As[buf][r0 + g    ][tg];
            af[mi][1] = As[buf][r0 + g + 8][tg];
            af[mi][2] = As[buf][r0 + g    ][tg + 4];
            af[mi][3] = As[buf][r0 + g + 8][tg + 4];
        }
        uint32_t bfr[4][2];
#pragma unroll
        for (int ni = 0; ni < 4; ni++) {
            int c0 = wx*32 + ni*8;
            bfr[ni][0] = Bs[buf][c0 + g][tg];
            bfr[ni][1] = Bs[buf][c0 + g][tg + 4];
        }
#pragma unroll
        for (int mi = 0; mi < 4; mi++)
#pragma unroll
            for (int ni = 0; ni < 4; ni++)
                mma_bf16(acc[mi][ni], af[mi], bfr[ni]);

        if (pf) {
            int nb = buf ^ 1;
            if (aPacked) {
                As[nb][ar][aw+0] = wa.x; As[nb][ar][aw+1] = wa.y;
                As[nb][ar][aw+2] = wa.z; As[nb][ar][aw+3] = wa.w;
            } else {
                As[nb][ar][aw+0] = pkbf(a0.x, a0.y);
                As[nb][ar][aw+1] = pkbf(a0.z, a0.w);
                As[nb][ar][aw+2] = pkbf(a1.x, a1.y);
                As[nb][ar][aw+3] = pkbf(a1.z, a1.w);
            }
            Bs[nb][bn0+0][bkp] = pkbf(b0.x, b1.x);
            Bs[nb][bn0+1][bkp] = pkbf(b0.y, b1.y);
            Bs[nb][bn0+2][bkp] = pkbf(b0.z, b1.z);
            Bs[nb][bn0+3][bkp] = pkbf(b0.w, b1.w);
        }
        __syncthreads();
        buf ^= 1;
    }

#pragma unroll
    for (int mi = 0; mi < 4; mi++) {
#pragma unroll
        for (int half = 0; half < 2; half++) {
            int r = bm + wy*64 + mi*16 + g + half*8;
            if (r >= M) continue;
#pragma unroll
            for (int ni = 0; ni < 4; ni++) {
                int c = bn + wx*32 + ni*8 + 2*tg;
                float v0 = acc[mi][ni][half*2+0] + (bias ? bias[c]   : 0.f);
                float v1 = acc[mi][ni][half*2+1] + (bias ? bias[c+1] : 0.f);
                if (act == 1) { v0 = fmaxf(v0, 0.f); v1 = fmaxf(v1, 0.f); }
                if (act == 2) {
                    int rr = r - PADT;
                    if (rr >= 0) {
                        float2* p = (float2*)(C + (size_t)rr*N + c);
                        float2 cur = *p;
                        cur.x += v0; cur.y += v1;
                        *p = cur;
                    }
                } else if (act == 4) {
                    ((uint32_t*)C)[(size_t)r*(N >> 1) + (c >> 1)] = pkbf(v0, v1);
                } else {
                    *(float2*)(C + (size_t)r*N + c) = make_float2(v0, v1);
                }
            }
        }
    }
}

// ==================== tf32 tensor-core GEMM (pinv path), 128x128x8 ====================
__global__ __launch_bounds__(256) void tf32gemm_k(
    const float* __restrict__ A, const float* __restrict__ B,
    float* __restrict__ C, int Kd, size_t sAB,
    float cI, float eB, float sc)
{
    __shared__ uint32_t As[2][8][136];
    __shared__ uint32_t Bs[2][8][136];
    A += (size_t)blockIdx.z * sAB;
    B += (size_t)blockIdx.z * sAB;
    C += (size_t)blockIdx.z * sAB;
    const int N = 256;
    int bm = blockIdx.y * 128, bn = blockIdx.x * 128;
    int tid = threadIdx.x;
    int arow = tid >> 1, acol = (tid & 1) << 2;
    int brow = tid >> 5, bcol = (tid & 31) << 2;
    int wid = tid >> 5, lane = tid & 31;
    int wy = wid >> 2, wx = wid & 3;
    int g = lane >> 2, tg = lane & 3;

    float acc[4][4][4];
#pragma unroll
    for (int mi = 0; mi < 4; mi++)
#pragma unroll
        for (int ni = 0; ni < 4; ni++)
#pragma unroll
            for (int q = 0; q < 4; q++) acc[mi][ni][q] = 0.f;

    int nk = Kd >> 3;
    int col0 = bn + bcol;

    {
        float4 va = *(const float4*)(A + (size_t)(bm + arow)*Kd + acol);
        As[0][acol+0][arow] = f2tf32(va.x);
        As[0][acol+1][arow] = f2tf32(va.y);
        As[0][acol+2][arow] = f2tf32(va.z);
        As[0][acol+3][arow] = f2tf32(va.w);
        float4 vb = *(const float4*)(B + (size_t)brow*N + col0);
        float e0 = eB*vb.x, e1 = eB*vb.y, e2 = eB*vb.z, e3 = eB*vb.w;
        if (brow == col0    ) e0 += cI;
        if (brow == col0 + 1) e1 += cI;
        if (brow == col0 + 2) e2 += cI;
        if (brow == col0 + 3) e3 += cI;
        Bs[0][brow][bcol  ] = f2tf32(e0);
        Bs[0][brow][bcol+1] = f2tf32(e1);
        Bs[0][brow][bcol+2] = f2tf32(e2);
        Bs[0][brow][bcol+3] = f2tf32(e3);
    }
    __syncthreads();

    int buf = 0;
    for (int kt = 0; kt < nk; kt++) {
        float4 va, vb;
        bool pf = (kt + 1 < nk);
        if (pf) {
            int k0 = (kt + 1) << 3;
            va = *(const float4*)(A + (size_t)(bm + arow)*Kd + k0 + acol);
            vb = *(const float4*)(B + (size_t)(k0 + brow)*N + col0);
        }
        uint32_t af[4][4];
#pragma unroll
        for (int mi = 0; mi < 4; mi++) {
            int r0 = wy*64 + mi*16;
            af[mi][0] = As[buf][tg  ][r0 + g];
            af[mi][1] = As[buf][tg  ][r0 + g + 8];
            af[mi][2] = As[buf][tg+4][r0 + g];
            af[mi][3] = As[buf][tg+4][r0 + g + 8];
        }
        uint32_t bfr[4][2];
#pragma unroll
        for (int ni = 0; ni < 4; ni++) {
            int c0 = wx*32 + ni*8;
            bfr[ni][0] = Bs[buf][tg  ][c0 + g];
            bfr[ni][1] = Bs[buf][tg+4][c0 + g];
        }
#pragma unroll
        for (int mi = 0; mi < 4; mi++)
#pragma unroll
            for (int ni = 0; ni < 4; ni++)
                mma_tf32(acc[mi][ni], af[mi], bfr[ni]);

        if (pf) {
            int nb = buf ^ 1;
            int kr = ((kt + 1) << 3) + brow;
            As[nb][acol+0][arow] = f2tf32(va.x);
            As[nb][acol+1][arow] = f2tf32(va.y);
            As[nb][acol+2][arow] = f2tf32(va.z);
            As[nb][acol+3][arow] = f2tf32(va.w);
            float e0 = eB*vb.x, e1 = eB*vb.y, e2 = eB*vb.z, e3 = eB*vb.w;
            if (kr == col0    ) e0 += cI;
            if (kr == col0 + 1) e1 += cI;
            if (kr == col0 + 2) e2 += cI;
            if (kr == col0 + 3) e3 += cI;
            Bs[nb][brow][bcol  ] = f2tf32(e0);
            Bs[nb][brow][bcol+1] = f2tf32(e1);
            Bs[nb][brow][bcol+2] = f2tf32(e2);
            Bs[nb][brow][bcol+3] = f2tf32(e3);
        }
        __syncthreads();
        buf ^= 1;
    }

#pragma unroll
    for (int mi = 0; mi < 4; mi++) {
#pragma unroll
        for (int half = 0; half < 2; half++) {
            int r = bm + wy*64 + mi*16 + g + half*8;
#pragma unroll
            for (int ni = 0; ni < 4; ni++) {
                int c = bn + wx*32 + ni*8 + 2*tg;
                *(float2*)(C + (size_t)r*N + c) =
                    make_float2(sc*acc[mi][ni][half*2+0], sc*acc[mi][ni][half*2+1]);
            }
        }
    }
}

// ==================== fused attention (bf16), 64-wide chunks ====================
#define SW_QS 0
#define SW_KS 4608
#define SW_VS 6912
#define SW_PS 9216
#define SW_RS 13824
#define SM_FUSED_BYTES ((13824 + 4608 + 128)*4)

__global__ __launch_bounds__(256) void a3_fused_k() {
    extern __shared__ uint32_t sm[];
    uint32_t* qs = sm + SW_QS;
    uint32_t* Ks = sm + SW_KS;
    uint32_t* Vs = sm + SW_VS;
    uint32_t* Ps = sm + SW_PS;
    float* rsm = (float*)(sm + SW_RS);

    int split = blockIdx.x;
    int bm = blockIdx.y * 128;
    int z = blockIdx.z; int zb = z / NH, zh = z % NH;
    int tid = threadIdx.x;
    int wid = tid >> 5, lane = tid & 31;
    int wy = wid >> 2, wx = wid & 3;
    int wy2 = wid >> 1, wx2 = wid & 1;
    int g = lane >> 2, tg = lane & 3;

    if (tid < 128) rsm[tid] = 0.f;

    for (int i = tid; i < 128*16; i += 256) {
        int row = i >> 4, f4 = (i & 15) << 2;
        float4 v = *(const float4*)(d_ql + ((size_t)(z*ML + bm + row))*DH + f4);
        qs[row*36 + (f4>>1)    ] = pkbf(v.x, v.y);
        qs[row*36 + (f4>>1) + 1] = pkbf(v.z, v.w);
    }

    float acc_o[2][4][4];
#pragma unroll
    for (int a = 0; a < 2; a++)
#pragma unroll
        for (int b = 0; b < 4; b++)
#pragma unroll
            for (int q = 0; q < 4; q++) acc_o[a][b][q] = 0.f;
    float rs_loc[8];
#pragma unroll
    for (int a = 0; a < 8; a++) rs_loc[a] = 0.f;

    for (int ci = 0; ci < 12; ci++) {
        int c0 = split*768 + ci*64;
        for (int i = tid; i < 64*8; i += 256) {
            int tok = i >> 3, p4 = (i & 7) << 2;
            uint4 w = *(const uint4*)(d_qkvh + ((size_t)(zb*NP + c0 + tok))*768 + 256 + zh*32 + p4);
            Ks[tok*36 + p4+0] = w.x;
            Ks[tok*36 + p4+1] = w.y;
            Ks[tok*36 + p4+2] = w.z;
            Ks[tok*36 + p4+3] = w.w;
        }
        for (int i = tid; i < 32*8; i += 256) {
            int tp = i >> 3, p4 = (i & 7) << 2;
            const uint32_t* vb0 = d_qkvh + ((size_t)(zb*NP + c0 + 2*tp))*768 + 512 + zh*32 + p4;
            uint4 wa = *(const uint4*)vb0;
            uint4 wb = *(const uint4*)(vb0 + 768);
            Vs[(2*(p4+0)  )*36 + tp] = __byte_perm(wa.x, wb.x, 0x5410);
            Vs[(2*(p4+0)+1)*36 + tp] = __byte_perm(wa.x, wb.x, 0x7632);
            Vs[(2*(p4+1)  )*36 + tp] = __byte_perm(wa.y, wb.y, 0x5410);
            Vs[(2*(p4+1)+1)*36 + tp] = __byte_perm(wa.y, wb.y, 0x7632);
            Vs[(2*(p4+2)  )*36 + tp] = __byte_perm(wa.z, wb.z, 0x5410);
            Vs[(2*(p4+2)+1)*36 + tp] = __byte_perm(wa.z, wb.z, 0x7632);
            Vs[(2*(p4+3)  )*36 + tp] = __byte_perm(wa.w, wb.w, 0x5410);
            Vs[(2*(p4+3)+1)*36 + tp] = __byte_perm(wa.w, wb.w, 0x7632);
        }
        __syncthreads();

        float acc_s[4][2][4];
#pragma unroll
        for (int a = 0; a < 4; a++)
#pragma unroll
            for (int b = 0; b < 2; b++)
#pragma unroll
                for (int q = 0; q < 4; q++) acc_s[a][b][q] = 0.f;

#pragma unroll
        for (int kk = 0; kk < 4; kk++) {
            uint32_t af[4][4], bfr[2][2];
#pragma unroll
            for (int mi = 0; mi < 4; mi++) {
                int r0 = wy*64 + mi*16;
                af[mi][0] = qs[(r0 + g    )*36 + kk*8 + tg];
                af[mi][1] = qs[(r0 + g + 8)*36 + kk*8 + tg];
                af[mi][2] = qs[(r0 + g    )*36 + kk*8 + tg + 4];
                af[mi][3] = qs[(r0 + g + 8)*36 + kk*8 + tg + 4];
            }
#pragma unroll
            for (int ni = 0; ni < 2; ni++) {
                int cw = wx*16 + ni*8;
                bfr[ni][0] = Ks[(cw + g)*36 + kk*8 + tg];
                bfr[ni][1] = Ks[(cw + g)*36 + kk*8 + tg + 4];
            }
#pragma unroll
            for (int mi = 0; mi < 4; mi++)
#pragma unroll
                for (int ni = 0; ni < 2; ni++)
                    mma_bf16(acc_s[mi][ni], af[mi], bfr[ni]);
        }

#pragma unroll
        for (int mi = 0; mi < 4; mi++)
#pragma unroll
            for (int half = 0; half < 2; half++) {
                int rl = wy*64 + mi*16 + half*8 + g;
                float ra = 0.f;
#pragma unroll
                for (int ni = 0; ni < 2; ni++) {
                    int cp = wx*8 + ni*4 + tg;
                    float v0 = __expf(acc_s[mi][ni][half*2+0]);
                    float v1 = __expf(acc_s[mi][ni][half*2+1]);
                    Ps[rl*36 + cp] = pkbf(v0, v1);
                    ra += v0 + v1;
                }
                rs_loc[mi*2 + half] += ra;
            }
        __syncthreads();

#pragma unroll
        for (int kk = 0; kk < 4; kk++) {
            uint32_t af2[2][4], bf2[4][2];
#pragma unroll
            for (int mi2 = 0; mi2 < 2; mi2++) {
                int m0 = wy2*32 + mi2*16;
                af2[mi2][0] = Ps[(m0 + g    )*36 + kk*8 + tg];
                af2[mi2][1] = Ps[(m0 + g + 8)*36 + kk*8 + tg];
                af2[mi2][2] = Ps[(m0 + g    )*36 + kk*8 + tg + 4];
                af2[mi2][3] = Ps[(m0 + g + 8)*36 + kk*8 + tg + 4];
            }
#pragma unroll
            for (int ni2 = 0; ni2 < 4; ni2++) {
                int cw = wx2*32 + ni2*8;
                bf2[ni2][0] = Vs[(cw + g)*36 + kk*8 + tg];
                bf2[ni2][1] = Vs[(cw + g)*36 + kk*8 + tg + 4];
            }
#pragma unroll
            for (int mi2 = 0; mi2 < 2; mi2++)
#pragma unroll
                for (int ni2 = 0; ni2 < 4; ni2++)
                    mma_bf16(acc_o[mi2][ni2], af2[mi2], bf2[ni2]);
        }
        __syncthreads();
    }

#pragma unroll
    for (int j2 = 0; j2 < 8; j2++) {
        int rl = wy*64 + (j2>>1)*16 + (j2&1)*8 + g;
        atomicAdd(&rsm[rl], rs_loc[j2]);
    }
    __syncthreads();
    if (tid < 128) atomicAdd(d_rs + (size_t)z*ML + bm + tid, rsm[tid]);
#pragma unroll
    for (int mi2 = 0; mi2 < 2; mi2++)
#pragma unroll
        for (int half = 0; half < 2; half++) {
            int m = wy2*32 + mi2*16 + half*8 + g;
#pragma unroll
            for (int ni2 = 0; ni2 < 4; ni2++) {
                int cc = wx2*32 + ni2*8 + 2*tg;
                float* dst = d_a3v + ((size_t)(z*ML + bm + m))*DH + cc;
                atomicAdd(dst,     acc_o[mi2][ni2][half*2+0]);
                atomicAdd(dst + 1, acc_o[mi2][ni2][half*2+1]);
            }
        }
}

__global__ __launch_bounds__(256) void a1_fused_k() {
    extern __shared__ uint32_t sm[];
    uint32_t* qs = sm + SW_QS;
    uint32_t* Ks = sm + SW_KS;
    uint32_t* Vs = sm + SW_VS;
    uint32_t* Ps = sm + SW_PS;
    float* rsm = (float*)(sm + SW_RS);

    int bm = blockIdx.x * 128;
    int z = blockIdx.y; int zb = z / NH, zh = z % NH;
    int tid = threadIdx.x;
    int wid = tid >> 5, lane = tid & 31;
    int wy = wid >> 2, wx = wid & 3;
    int wy2 = wid >> 1, wx2 = wid & 1;
    int g = lane >> 2, tg = lane & 3;

    const uint32_t EIGHTH = 0x3E003E00u;

    if (tid < 128) rsm[tid] = 0.f;

    for (int i = tid; i < 128*8; i += 256) {
        int row = i >> 3, p4 = (i & 7) << 2;
        uint4 w = *(const uint4*)(d_qkvh + ((size_t)(zb*NP + bm + row))*768 + zh*32 + p4);
        qs[row*36 + p4+0] = mulbf2(w.x, EIGHTH);
        qs[row*36 + p4+1] = mulbf2(w.y, EIGHTH);
        qs[row*36 + p4+2] = mulbf2(w.z, EIGHTH);
        qs[row*36 + p4+3] = mulbf2(w.w, EIGHTH);
    }

    float acc_o[2][4][4];
#pragma unroll
    for (int a = 0; a < 2; a++)
#pragma unroll
        for (int b = 0; b < 4; b++)
#pragma unroll
            for (int q = 0; q < 4; q++) acc_o[a][b][q] = 0.f;
    float rs_loc[8];
#pragma unroll
    for (int a = 0; a < 8; a++) rs_loc[a] = 0.f;

    for (int lc = 0; lc < 4; lc++) {
        int base = lc*64;
        for (int i = tid; i < 64*16; i += 256) {
            int lm = i >> 4, f4 = (i & 15) << 2;
            float4 kv = *(const float4*)(d_kl + ((size_t)(z*ML + base + lm))*DH + f4);
            Ks[lm*36 + (f4>>1)    ] = pkbf(kv.x, kv.y);
            Ks[lm*36 + (f4>>1) + 1] = pkbf(kv.z, kv.w);
        }
        for (int i = tid; i < 32*16; i += 256) {
            int lp = i >> 4, f4 = (i & 15) << 2;
            const float* wb0 = d_w2 + ((size_t)(z*ML + base + 2*lp))*DH + f4;
            float4 w0 = *(const float4*)wb0;
            float4 w1 = *(const float4*)(wb0 + DH);
            Vs[(f4+0)*36 + lp] = pkbf(w0.x, w1.x);
            Vs[(f4+1)*36 + lp] = pkbf(w0.y, w1.y);
            Vs[(f4+2)*36 + lp] = pkbf(w0.z, w1.z);
            Vs[(f4+3)*36 + lp] = pkbf(w0.w, w1.w);
        }
        __syncthreads();

        float acc_s[4][2][4];
#pragma unroll
        for (int a = 0; a < 4; a++)
#pragma unroll
            for (int b = 0; b < 2; b++)
#pragma unroll
                for (int q = 0; q < 4; q++) acc_s[a][b][q] = 0.f;

#pragma unroll
        for (int kk = 0; kk < 4; kk++) {
            uint32_t af[4][4], bfr[2][2];
#pragma unroll
            for (int mi = 0; mi < 4; mi++) {
                int r0 = wy*64 + mi*16;
                af[mi][0] = qs[(r0 + g    )*36 + kk*8 + tg];
                af[mi][1] = qs[(r0 + g + 8)*36 + kk*8 + tg];
                af[mi][2] = qs[(r0 + g    )*36 + kk*8 + tg + 4];
                af[mi][3] = qs[(r0 + g + 8)*36 + kk*8 + tg + 4];
            }
#pragma unroll
            for (int ni = 0; ni < 2; ni++) {
                int cw = wx*16 + ni*8;
                bfr[ni][0] = Ks[(cw + g)*36 + kk*8 + tg];
                bfr[ni][1] = Ks[(cw + g)*36 + kk*8 + tg + 4];
            }
#pragma unroll
            for (int mi = 0; mi < 4; mi++)
#pragma unroll
                for (int ni = 0; ni < 2; ni++)
                    mma_bf16(acc_s[mi][ni], af[mi], bfr[ni]);
        }

#pragma unroll
        for (int mi = 0; mi < 4; mi++)
#pragma unroll
            for (int half = 0; half < 2; half++) {
                int rl = wy*64 + mi*16 + half*8 + g;
                float ra = 0.f;
#pragma unroll
                for (int ni = 0; ni < 2; ni++) {
                    int cp = wx*8 + ni*4 + tg;
                    float v0 = __expf(acc_s[mi][ni][half*2+0]);
                    float v1 = __expf(acc_s[mi][ni][half*2+1]);
                    Ps[rl*36 + cp] = pkbf(v0, v1);
                    ra += v0 + v1;
                }
                rs_loc[mi*2 + half] += ra;
            }
        __syncthreads();

#pragma unroll
        for (int kk = 0; kk < 4; kk++) {
            uint32_t af2[2][4], bf2[4][2];
#pragma unroll
            for (int mi2 = 0; mi2 < 2; mi2++) {
                int m0 = wy2*32 + mi2*16;
                af2[mi2][0] = Ps[(m0 + g    )*36 + kk*8 + tg];
                af2[mi2][1] = Ps[(m0 + g + 8)*36 + kk*8 + tg];
                af2[mi2][2] = Ps[(m0 + g    )*36 + kk*8 + tg + 4];
                af2[mi2][3] = Ps[(m0 + g + 8)*36 + kk*8 + tg + 4];
            }
#pragma unroll
            for (int ni2 = 0; ni2 < 4; ni2++) {
                int cw = wx2*32 + ni2*8;
                bf2[ni2][0] = Vs[(cw + g)*36 + kk*8 + tg];
                bf2[ni2][1] = Vs[(cw + g)*36 + kk*8 + tg + 4];
            }
#pragma unroll
            for (int mi2 = 0; mi2 < 2; mi2++)
#pragma unroll
                for (int ni2 = 0; ni2 < 4; ni2++)
                    mma_bf16(acc_o[mi2][ni2], af2[mi2], bf2[ni2]);
        }
        __syncthreads();
    }

#pragma unroll
    for (int j2 = 0; j2 < 8; j2++) {
        int rl = wy*64 + (j2>>1)*16 + (j2&1)*8 + g;
        atomicAdd(&rsm[rl], rs_loc[j2]);
    }
    __syncthreads();
#pragma unroll
    for (int mi2 = 0; mi2 < 2; mi2++)
#pragma unroll
        for (int half = 0; half < 2; half++) {
            int m = wy2*32 + mi2*16 + half*8 + g;
            float inv = 1.f / rsm[m];
#pragma unroll
            for (int ni2 = 0; ni2 < 4; ni2++) {
                int cc = wx2*32 + ni2*8 + 2*tg;
                d_attnh[(size_t)(zb*NP + bm + m)*256 + ((zh*64 + cc) >> 1)] =
                    pkbf(acc_o[mi2][ni2][half*2+0]*inv, acc_o[mi2][ni2][half*2+1]*inv);
            }
        }
}

// -------------------- small 64-tile batched GEMM (fp32) with optional B row-scale --------------------
__global__ __launch_bounds__(256) void bgemm_epi(
    const float* __restrict__ A, const float* __restrict__ Bm, float* __restrict__ C,
    int Md, int Nd, int Kd, float cI, float eB, float s, const float* __restrict__ rsc)
{
    __shared__ float As[16][64];
    __shared__ float Bs[16][64];
    A  += (size_t)blockIdx.z * Md * Kd;
    Bm += (size_t)blockIdx.z * Kd * Nd;
    C  += (size_t)blockIdx.z * Md * Nd;
    const float* rscz = rsc ? rsc + (size_t)blockIdx.z * Kd : nullptr;
    int bm = blockIdx.y * 64, bn = blockIdx.x * 64;
    int tid = threadIdx.x;
    int la_r = tid >> 2, la_c = (tid & 3) << 2;
    int lb_r = tid >> 4, lb_c = (tid & 15) << 2;
    int ty = tid >> 4, tx = tid & 15;
    float acc[4][4];
#pragma unroll
    for (int i = 0; i < 4; i++)
#pragma unroll
        for (int j = 0; j < 4; j++) acc[i][j] = 0.f;

    for (int k0 = 0; k0 < Kd; k0 += 16) {
        float4 av = *(const float4*)(A + (size_t)(bm + la_r)*Kd + k0 + la_c);
        As[la_c  ][la_r] = av.x;
        As[la_c+1][la_r] = av.y;
        As[la_c+2][la_r] = av.z;
        As[la_c+3][la_r] = av.w;
        int kr = k0 + lb_r;
        float4 bv = *(const float4*)(Bm + (size_t)kr*Nd + bn + lb_c);
        float rsv = rscz ? (1.f / rscz[kr]) : 1.f;
        float e0 = eB*rsv*bv.x, e1 = eB*rsv*bv.y, e2 = eB*rsv*bv.z, e3 = eB*rsv*bv.w;
        int c0 = bn + lb_c;
        if (kr == c0    ) e0 += cI;
        if (kr == c0 + 1) e1 += cI;
        if (kr == c0 + 2) e2 += cI;
        if (kr == c0 + 3) e3 += cI;
        Bs[lb_r][lb_c  ] = e0;
        Bs[lb_r][lb_c+1] = e1;
        Bs[lb_r][lb_c+2] = e2;
        Bs[lb_r][lb_c+3] = e3;
        __syncthreads();
#pragma unroll
        for (int kk = 0; kk < 16; kk++) {
            float a0 = As[kk][ty*4+0], a1 = As[kk][ty*4+1], a2 = As[kk][ty*4+2], a3 = As[kk][ty*4+3];
            float b0 = Bs[kk][tx*4+0], b1 = Bs[kk][tx*4+1], b2 = Bs[kk][tx*4+2], b3 = Bs[kk][tx*4+3];
            acc[0][0]+=a0*b0; acc[0][1]+=a0*b1; acc[0][2]+=a0*b2; acc[0][3]+=a0*b3;
            acc[1][0]+=a1*b0; acc[1][1]+=a1*b1; acc[1][2]+=a1*b2; acc[1][3]+=a1*b3;
            acc[2][0]+=a2*b0; acc[2][1]+=a2*b1; acc[2][2]+=a2*b2; acc[2][3]+=a2*b3;
            acc[3][0]+=a3*b0; acc[3][1]+=a3*b1; acc[3][2]+=a3*b2; acc[3][3]+=a3*b3;
        }
        __syncthreads();
    }
#pragma unroll
    for (int i = 0; i < 4; i++) {
        int r = bm + ty*4 + i;
#pragma unroll
        for (int j = 0; j < 4; j++) {
            int c = bn + tx*4 + j;
            C[(size_t)r*Nd + c] = s * acc[i][j];
        }
    }
}

// -------------------- misc small kernels --------------------
__global__ void fill_cls_k(const float* __restrict__ cls) {
    int i = blockIdx.x*256 + threadIdx.x;
    if (i < BB*EMBD) d_h[(size_t)(i/EMBD)*NT*EMBD + (i % EMBD)] = cls[i % EMBD];
}

__global__ void fill_wrap_k() {
    int i = blockIdx.x*256 + threadIdx.x;
    if (i >= BB*ADDW*EMBD) return;
    int c = i % EMBD; int r = i / EMBD; int j = r % ADDW; int b = r / ADDW;
    d_h[((size_t)(b*NT + 1 + N0 + j))*EMBD + c] = d_h[((size_t)(b*NT + 1 + j))*EMBD + c];
}

// copy cls row from d_h into d_h2 (layer-2 residual buffer)
__global__ void copy_cls_k() {
    int i = blockIdx.x*256 + threadIdx.x;
    if (i >= BB*EMBD) return;
    int b = i / EMBD, c = i % EMBD;
    d_h2[(size_t)b*NT*EMBD + c] = d_h[(size_t)b*NT*EMBD + c];
}

// layernorm: one warp per row, shuffle reductions, bf16x2-packed output; residual source h
__global__ __launch_bounds__(256) void ln_pad_k2(const float* __restrict__ h,
                                                 const float* __restrict__ g, const float* __restrict__ bp) {
    int tid = threadIdx.x, wid = tid >> 5, lane = tid & 31;
    int row = blockIdx.x*8 + wid;
    int b = row / NP, t = row % NP;
    uint32_t* out = d_xnh + (size_t)row*256;
    if (t < PADT) {
#pragma unroll
        for (int k = 0; k < 4; k++)
            *(uint2*)(out + k*64 + lane*2) = make_uint2(0u, 0u);
        return;
    }
    const float* x = h + ((size_t)b*NT + (t - PADT))*EMBD;
    float4 v[4];
    float s = 0.f;
#pragma unroll
    for (int k = 0; k < 4; k++) {
        v[k] = *(const float4*)(x + k*128 + lane*4);
        s += v[k].x + v[k].y + v[k].z + v[k].w;
    }
#pragma unroll
    for (int o = 16; o > 0; o >>= 1) s += __shfl_xor_sync(0xffffffffu, s, o);
    float mean = s * (1.f/512.f);
    float s2 = 0.f;
#pragma unroll
    for (int k = 0; k < 4; k++) {
        v[k].x -= mean; v[k].y -= mean; v[k].z -= mean; v[k].w -= mean;
        s2 += v[k].x*v[k].x + v[k].y*v[k].y + v[k].z*v[k].z + v[k].w*v[k].w;
    }
#pragma unroll
    for (int o = 16; o > 0; o >>= 1) s2 += __shfl_xor_sync(0xffffffffu, s2, o);
    float inv = rsqrtf(s2 * (1.f/512.f) + 1e-5f);
#pragma unroll
    for (int k = 0; k < 4; k++) {
        float4 gv = *(const float4*)(g  + k*128 + lane*4);
        float4 bv = *(const float4*)(bp + k*128 + lane*4);
        uint2 o2;
        o2.x = pkbf(v[k].x*inv*gv.x + bv.x, v[k].y*inv*gv.y + bv.y);
        o2.y = pkbf(v[k].z*inv*gv.z + bv.z, v[k].w*inv*gv.w + bv.w);
        *(uint2*)(out + k*64 + lane*2) = o2;
    }
}

__global__ void landmarks_k() {
    int blk = blockIdx.x; int bh = blk >> 8; int i = blk & 255;
    int d = threadIdx.x;
    int b = bh / NH, h = bh % NH;
    int p = d >> 1, hi = d & 1;
    const uint32_t* base = d_qkvh + ((size_t)(b*NP) + (size_t)i*LWIN)*768 + h*32 + p;
    float sq = 0.f, sk = 0.f;
#pragma unroll
    for (int j = 0; j < LWIN; j++) {
        uint32_t wq = base[(size_t)j*768];
        uint32_t wk = base[(size_t)j*768 + 256];
        sq += hi ? bhi(wq) : blo(wq);
        sk += hi ? bhi(wk) : blo(wk);
    }
    d_ql[((size_t)(bh*ML + i))*DH + d] = sq * (0.125f / LWIN);
    d_kl[((size_t)(bh*ML + i))*DH + d] = sk * (1.f   / LWIN);
}

__global__ __launch_bounds__(256) void a2_k() {
    int blk = blockIdx.x; int bh = blk >> 8; int i = blk & 255;
    int tid = threadIdx.x;
    __shared__ float sq[64];
    __shared__ float red[256];
    if (tid < 64) sq[tid] = d_ql[((size_t)(bh*ML + i))*DH + tid];
    __syncthreads();
    float s = dot64(sq, d_kl + ((size_t)(bh*ML + tid))*DH);
    red[tid] = s; __syncthreads();
    for (int o = 128; o > 0; o >>= 1) { if (tid < o) red[tid] = fmaxf(red[tid], red[tid+o]); __syncthreads(); }
    float m = red[0]; __syncthreads();
    float p = expf(s - m);
    red[tid] = p; __syncthreads();
    for (int o = 128; o > 0; o >>= 1) { if (tid < o) red[tid] += red[tid+o]; __syncthreads(); }
    float Z = red[0];
    d_a2[((size_t)bh << 16) + ((size_t)i << 8) + tid] = p / Z;
}

// per-bh max column sum, plain store (overwritten each layer, no reset needed)
__global__ __launch_bounds__(256) void a2_stats_k() {
    int bh = blockIdx.x; int tid = threadIdx.x;
    const float* a = d_a2 + ((size_t)bh << 16);
    float cs = 0.f;
    for (int i = 0; i < ML; i++) cs += a[(size_t)i*ML + tid];
    __shared__ float red[256];
    red[tid] = cs; __syncthreads();
    for (int o = 128; o > 0; o >>= 1) { if (tid < o) red[tid] = fmaxf(red[tid], red[tid+o]); __syncthreads(); }
    if (tid == 0) d_mxb[bh] = red[0];
}

__global__ void z_init_k() {
    __shared__ float denom_s;
    if (threadIdx.x == 0) {
        float m = d_mxb[0];
#pragma unroll
        for (int i = 1; i < BH; i++) m = fmaxf(m, d_mxb[i]);
        denom_s = m;
    }
    __syncthreads();
    float denom = denom_s;
    size_t idx = (size_t)blockIdx.x*256 + threadIdx.x;
    if (idx >= (size_t)BH*ML*ML) return;
    size_t bh = idx >> 16; size_t r = (idx >> 8) & 255; size_t c = idx & 255;
    d_z0[idx] = d_a2[(bh << 16) + (c << 8) + r] / denom;
}

// conv residual: V bf16 in, RMW on packed bf16 attn
__global__ __launch_bounds__(256) void conv_res_k(const float* __restrict__ w) {
    __shared__ float vs[160*64];
    __shared__ float ws[33];
    int blk = blockIdx.x;
    int strip = blk % 48; int bh = blk / 48; int h = bh % NH; int b = bh / NH;
    int t0 = strip * 128;
    int tid = threadIdx.x;
    if (tid < 33) ws[tid] = w[h*33 + tid];
    for (int i = tid; i < 160*16; i += 256) {
        int row = i >> 4, f4 = (i & 15) << 2;
        int t = t0 - 16 + row;
        float4 v = make_float4(0.f,0.f,0.f,0.f);
        if (t >= 0 && t < NP) {
            uint2 wv = *(const uint2*)(d_qkvh + ((size_t)(b*NP + t))*768 + 512 + h*32 + (f4 >> 1));
            v.x = blo(wv.x); v.y = bhi(wv.x); v.z = blo(wv.y); v.w = bhi(wv.y);
        }
        *(float4*)(vs + row*64 + f4) = v;
    }
    __syncthreads();
#pragma unroll
    for (int j = 0; j < 8; j++) {
        int o = tid + j*256;
        int row = o >> 4, f4 = (o & 15) << 2;
        float4 s = make_float4(0.f,0.f,0.f,0.f);
#pragma unroll
        for (int k = 0; k < 33; k++) {
            float4 v = *(const float4*)(vs + (row + k)*64 + f4);
            float wk = ws[k];
            s.x += v.x*wk; s.y += v.y*wk; s.z += v.z*wk; s.w += v.w*wk;
        }
        uint2* dst = (uint2*)(d_attnh + (size_t)(b*NP + t0 + row)*256 + ((h*64 + f4) >> 1));
        uint2 cur = *dst;
        cur.x = pkbf(blo(cur.x) + s.x, bhi(cur.x) + s.y);
        cur.y = pkbf(blo(cur.y) + s.z, bhi(cur.y) + s.w);
        *dst = cur;
    }
}

// combined PPEG weights
__global__ void wtrans_k(const float* __restrict__ w7, const float* __restrict__ w5,
                         const float* __restrict__ w3) {
    int i = blockIdx.x*256 + threadIdx.x;
    if (i >= 49*EMBD) return;
    int aq = i / EMBD, c = i % EMBD;
    int a = aq / 7, q = aq % 7;
    float v = w7[c*49 + aq];
    if (a >= 1 && a <= 5 && q >= 1 && q <= 5) v += w5[c*25 + (a-1)*5 + (q-1)];
    if (a >= 2 && a <= 4 && q >= 2 && q <= 4) v += w3[c*9  + (a-2)*3 + (q-2)];
    d_wct[i] = v;
}

// PPEG: row-tiled single 7x7 conv, reads d_h, writes DIRECTLY into d_h2 token rows
#define PP_SMEM_BYTES (7*84*32*4)
__global__ __launch_bounds__(256) void ppeg3_k(
    const float* __restrict__ b7, const float* __restrict__ b5, const float* __restrict__ b3)
{
    extern __shared__ float sb[];
    int cg = blockIdx.x;
    int i  = blockIdx.y;
    int b  = blockIdx.z;
    int tid = threadIdx.x;
    const float* hbase = d_h + ((size_t)(b*NT + 1))*EMBD + cg*32;
    for (int idx = tid; idx < 7*84*8; idx += 256) {
        int f4 = (idx & 7) << 2;
        int jj = (idx >> 3) % 84;
        int r  = idx / (84*8);
        int ii = i - 3 + r, px = jj - 3;
        float4 v = make_float4(0.f,0.f,0.f,0.f);
        if (ii >= 0 && ii < HW && px >= 0 && px < HW)
            v = *(const float4*)(hbase + (size_t)(ii*HW + px)*EMBD + f4);
        *(float4*)(sb + (r*84 + jj)*32 + f4) = v;
    }
    __syncthreads();
    int c = tid & 31, jgrp = tid >> 5;
    float wr[49];
#pragma unroll
    for (int t = 0; t < 49; t++) wr[t] = d_wct[t*EMBD + cg*32 + c];
    float bs = b7[cg*32 + c] + b5[cg*32 + c] + b3[cg*32 + c];
    for (int j = jgrp; j < HW; j += 8) {
        float s = sb[(3*84 + j + 3)*32 + c] + bs;
#pragma unroll
        for (int a = 0; a < 7; a++)
#pragma unroll
            for (int q = 0; q < 7; q++)
                s += sb[(a*84 + j + q)*32 + c] * wr[a*7 + q];
        d_h2[((size_t)(b*NT + 1) + i*HW + j)*EMBD + cg*32 + c] = s;
    }
}

__global__ __launch_bounds__(256) void head_k(
    const float* __restrict__ h,
    const float* __restrict__ g, const float* __restrict__ bp,
    const float* __restrict__ w, const float* __restrict__ bias, float* __restrict__ out)
{
    int b = blockIdx.x; int tid = threadIdx.x;
    __shared__ float xs[512];
    __shared__ float red[256];
    __shared__ float lg[4];
    const float* x = h + (size_t)b*NT*EMBD;
    float v0 = x[tid], v1 = x[tid+256];
    red[tid] = v0 + v1; __syncthreads();
    for (int o = 128; o > 0; o >>= 1) { if (tid < o) red[tid] += red[tid+o]; __syncthreads(); }
    float mean = red[0] * (1.f/512.f); __syncthreads();
    float e0 = v0 - mean, e1 = v1 - mean;
    red[tid] = e0*e0 + e1*e1; __syncthreads();
    for (int o = 128; o > 0; o >>= 1) { if (tid < o) red[tid] += red[tid+o]; __syncthreads(); }
    float inv = rsqrtf(red[0] * (1.f/512.f) + 1e-5f);
    xs[tid]     = e0*inv*g[tid]     + bp[tid];
    xs[tid+256] = e1*inv*g[tid+256] + bp[tid+256];
    __syncthreads();
    if (tid < 4) {
        float s = bias[tid];
        for (int k = 0; k < 512; k++) s += xs[k]*w[k*4 + tid];
        lg[tid] = s;
    }
    __syncthreads();
    if (tid == 0) {
        int best = 0; float bv = lg[0];
        for (int k = 1; k < 4; k++) if (lg[k] > bv) { bv = lg[k]; best = k; }
        float S = 1.f;
        for (int k = 0; k < 4; k++) {
            float hz = 1.f / (1.f + expf(-lg[k]));
            out[b*4 + k] = hz;
            S *= (1.f - hz);
            out[16 + b*4 + k] = S;
        }
        out[32 + b] = (float)best;
    }
}

// -------------------- host orchestration --------------------
static float* symaddr(const void* sym) { void* p = nullptr; cudaGetSymbolAddress(&p, sym); return (float*)p; }

static void attn_layer(float* hbuf,
                       const float* lng, const float* lnb, const float* qkvw,
                       const float* outw, const float* outb, const float* resw)
{
    float* xnhp  = symaddr(d_xnh);
    float* qkvp  = symaddr(d_qkvh);
    float* attnp = symaddr(d_attnh);
    float* a2p   = symaddr(d_a2);
    float* z0p   = symaddr(d_z0);
    float* z1p   = symaddr(d_z1);
    float* t0p   = symaddr(d_t0);
    float* t1p   = symaddr(d_t1);
    float* t2p   = symaddr(d_t2);
    float* a3vp  = symaddr(d_a3v);
    float* w2p   = symaddr(d_w2);
    float* rsp   = symaddr(d_rs);

    ln_pad_k2<<<BB*NP/8, 256>>>(hbuf, lng, lnb);
    bf16gemm_k<<<dim3(1536/128, NP/128, BB), 256>>>(
        xnhp, qkvw, nullptr, qkvp, NP, 1536, EMBD,
        (size_t)NP*256, (size_t)NP*768, 4, 1);
    landmarks_k<<<BH*ML, 64>>>();
    a2_k<<<BH*ML, 256>>>();
    a2_stats_k<<<BH, 256>>>();
    z_init_k<<<(BH*ML*ML + 255)/256, 256>>>();

    const size_t SB = (size_t)ML*ML;
    float* zin = z0p; float* zout = z1p;
    for (int it = 0; it < 6; it++) {
        tf32gemm_k<<<dim3(2, 2, BH), 256>>>(a2p, zin, t0p, 256, SB, 0.f,  1.f, 1.f);
        tf32gemm_k<<<dim3(2, 2, BH), 256>>>(t0p, t0p, t1p, 256, SB, 7.f, -1.f, 1.f);
        tf32gemm_k<<<dim3(2, 2, BH), 256>>>(t0p, t1p, t2p, 256, SB, 15.f,-1.f, 1.f);
        tf32gemm_k<<<dim3(2, 2, BH), 256>>>(zin, t2p, zout,256, SB, 13.f,-1.f, 0.25f);
        float* tmp = zin; zin = zout; zout = tmp;
    }
    // zin holds a2_inv (d_z0)

    cudaMemsetAsync(rsp, 0, (size_t)BH*ML*sizeof(float));
    cudaMemsetAsync(a3vp, 0, (size_t)BH*ML*DH*sizeof(float));
    a3_fused_k<<<dim3(8, 2, BH), 256, SM_FUSED_BYTES>>>();
    bgemm_epi<<<dim3(1, 4, BH), 256>>>(zin, a3vp, w2p, 256, 64, 256, 0.f, 1.f, 1.f, rsp);
    a1_fused_k<<<dim3(NP/128, BH), 256, SM_FUSED_BYTES>>>();

    conv_res_k<<<BB*NH*48, 256>>>(resw);
    // out projection: A packed (d_attnh), accumulate into residual buffer (act=2)
    bf16gemm_k<<<dim3(EMBD/128, NP/128, BB), 256>>>(
        attnp, outw, outb, hbuf, NP, EMBD, EMBD,
        (size_t)NP*256, (size_t)NT*EMBD, 2, 1);
}

extern "C" void kernel_launch(void* const* d_in, const int* in_sizes, int n_in,
                              void* d_out, int out_size)
{
    (void)in_sizes; (void)n_in; (void)out_size;
    const float* x_path = (const float*)d_in[0];
    const float* fc1_w  = (const float*)d_in[1];
    const float* fc1_b  = (const float*)d_in[2];
    const float* cls    = (const float*)d_in[3];
    const float* ln1g   = (const float*)d_in[4];
    const float* ln1b   = (const float*)d_in[5];
    const float* qkv1w  = (const float*)d_in[6];
    const float* out1w  = (const float*)d_in[7];
    const float* out1b  = (const float*)d_in[8];
    const float* res1w  = (const float*)d_in[9];
    const float* ln2g   = (const float*)d_in[10];
    const float* ln2b   = (const float*)d_in[11];
    const float* qkv2w  = (const float*)d_in[12];
    const float* out2w  = (const float*)d_in[13];
    const float* out2b  = (const float*)d_in[14];
    const float* res2w  = (const float*)d_in[15];
    const float* c7w    = (const float*)d_in[16];
    const float* c7b    = (const float*)d_in[17];
    const float* c5w    = (const float*)d_in[18];
    const float* c5b    = (const float*)d_in[19];
    const float* c3w    = (const float*)d_in[20];
    const float* c3b    = (const float*)d_in[21];
    const float* ng     = (const float*)d_in[22];
    const float* nb     = (const float*)d_in[23];
    const float* fc2w   = (const float*)d_in[24];
    const float* fc2b   = (const float*)d_in[25];
    float* out = (float*)d_out;

    static int cfg = 0;
    if (!cfg) {
        cudaFuncSetAttribute(a3_fused_k, cudaFuncAttributeMaxDynamicSharedMemorySize, SM_FUSED_BYTES);
        cudaFuncSetAttribute(a1_fused_k, cudaFuncAttributeMaxDynamicSharedMemorySize, SM_FUSED_BYTES);
        cudaFuncSetAttribute(ppeg3_k,    cudaFuncAttributeMaxDynamicSharedMemorySize, PP_SMEM_BYTES);
        cfg = 1;
    }

    float* hp  = symaddr(d_h);
    float* h2p = symaddr(d_h2);

    bf16gemm_k<<<dim3(EMBD/128, (N0 + 127)/128, BB), 256>>>(
        x_path, fc1_w, fc1_b, hp + EMBD, N0, EMBD, 1024,
        (size_t)N0*1024, (size_t)NT*EMBD, 1, 0);
    fill_cls_k<<<(BB*EMBD + 255)/256, 256>>>(cls);
    fill_wrap_k<<<(BB*ADDW*EMBD + 255)/256, 256>>>();
    wtrans_k<<<(49*EMBD + 255)/256, 256>>>(c7w, c5w, c3w);

    attn_layer(hp, ln1g, ln1b, qkv1w, out1w, out1b, res1w);

    ppeg3_k<<<dim3(16, HW, BB), 256, PP_SMEM_BYTES>>>(c7b, c5b, c3b);
    copy_cls_k<<<(BB*EMBD + 255)/256, 256>>>();

    attn_layer(h2p, ln2g, ln2b, qkv2w, out2w, out2b, res2w);

    head_k<<<BB, 256>>>(h2p, ng, nb, fc2w, fc2b, out);
}

// round 17
// speedup vs baseline: 1.0223x; 1.0154x over previous
#include <cuda_runtime.h>
#include <math.h>
#include <stdint.h>

#define BB   4
#define N0   6000
#define HW   78
#define NPIX (HW*HW)        // 6084
#define ADDW (NPIX - N0)    // 84
#define NT   (NPIX + 1)     // 6085
#define NP   6144
#define PADT (NP - NT)      // 59
#define EMBD 512
#define NH   8
#define DH   64
#define ML   256
#define LWIN (NP/ML)        // 24
#define BH   (BB*NH)        // 32

// -------------------- scratch (device globals, no allocation) --------------------
__device__ float    d_h    [(size_t)BB*NT*EMBD];    // residual stream, layer 1
__device__ float    d_h2   [(size_t)BB*NT*EMBD];    // residual stream, layer 2 (ppeg output)
__device__ uint32_t d_xnh  [(size_t)BB*NP*256];     // ln output, bf16x2 packed
__device__ uint32_t d_qkvh [(size_t)BB*NP*768];     // qkv bf16x2: [token][pair]
__device__ uint32_t d_attnh[(size_t)BB*NP*256];     // attention out, bf16x2 packed
__device__ float    d_ql  [BH*ML*DH];
__device__ float    d_kl  [BH*ML*DH];
__device__ float    d_a2  [BH*ML*ML];
__device__ float    d_z0  [BH*ML*ML];
__device__ float    d_z1  [BH*ML*ML];
__device__ float    d_t0  [BH*ML*ML];
__device__ float    d_t1  [BH*ML*ML];
__device__ float    d_t2  [BH*ML*ML];
__device__ float    d_a3v [BH*ML*DH];
__device__ float    d_w2  [BH*ML*DH];
__device__ float    d_rs  [BH*ML];
__device__ float    d_mxb [BH];                     // per-(b,h) col-sum max (plain stores)
__device__ float    d_wct [49*EMBD];

__device__ __forceinline__ float dot64(const float* __restrict__ a, const float* __restrict__ kp) {
    float s = 0.f;
#pragma unroll
    for (int i = 0; i < 16; i++) {
        float4 x = *(const float4*)(kp + 4*i);
        s += a[4*i]*x.x + a[4*i+1]*x.y + a[4*i+2]*x.z + a[4*i+3]*x.w;
    }
    return s;
}

__device__ __forceinline__ uint32_t f2tf32(float f) {
    uint32_t r;
    asm("cvt.rna.tf32.f32 %0, %1;" : "=r"(r) : "f"(f));
    return r;
}

__device__ __forceinline__ uint32_t pkbf(float lo, float hi) {
    uint32_t r;
    asm("cvt.rn.bf16x2.f32 %0, %1, %2;" : "=r"(r) : "f"(hi), "f"(lo));
    return r;
}

__device__ __forceinline__ float blo(uint32_t w) { return __uint_as_float(w << 16); }
__device__ __forceinline__ float bhi(uint32_t w) { return __uint_as_float(w & 0xffff0000u); }

__device__ __forceinline__ uint32_t mulbf2(uint32_t a, uint32_t b) {
    uint32_t r;
    asm("mul.bf16x2 %0, %1, %2;" : "=r"(r) : "r"(a), "r"(b));
    return r;
}

__device__ __forceinline__ void mma_tf32(float* c, const uint32_t* a, const uint32_t* b) {
    asm volatile("mma.sync.aligned.m16n8k8.row.col.f32.tf32.tf32.f32 "
        "{%0,%1,%2,%3}, {%4,%5,%6,%7}, {%8,%9}, {%0,%1,%2,%3};"
        : "+f"(c[0]), "+f"(c[1]), "+f"(c[2]), "+f"(c[3])
        : "r"(a[0]), "r"(a[1]), "r"(a[2]), "r"(a[3]), "r"(b[0]), "r"(b[1]));
}

__device__ __forceinline__ void mma_bf16(float* c, const uint32_t* a, const uint32_t* b) {
    asm volatile("mma.sync.aligned.m16n8k16.row.col.f32.bf16.bf16.f32 "
        "{%0,%1,%2,%3}, {%4,%5,%6,%7}, {%8,%9}, {%0,%1,%2,%3};"
        : "+f"(c[0]), "+f"(c[1]), "+f"(c[2]), "+f"(c[3])
        : "r"(a[0]), "r"(a[1]), "r"(a[2]), "r"(a[3]), "r"(b[0]), "r"(b[1]));
}

// ==================== bf16 tensor-core GEMM, 128x128x16 double-buffered ====================
// act: 0 plain fp32 out, 1 relu fp32 out, 2 accumulate into C with PADT row shift,
//      4 bf16x2-packed output (C as uint32*, row stride N/2 words)
// aPacked: A is bf16x2-packed (uint32*, row stride K/2 words, sA in words)
__global__ __launch_bounds__(256) void bf16gemm_k(
    const float* __restrict__ A, const float* __restrict__ B,
    const float* __restrict__ bias, float* __restrict__ C,
    int M, int N, int K, size_t sA, size_t sC, int act, int aPacked)
{
    __shared__ uint32_t As[2][128][12];
    __shared__ uint32_t Bs[2][128][12];
    A += (size_t)blockIdx.z * sA;
    C += (size_t)blockIdx.z * sC;
    int bm = blockIdx.y * 128, bn = blockIdx.x * 128;
    int tid = threadIdx.x;
    int ar = tid >> 1, ak = (tid & 1) << 3;
    int aw = (tid & 1) << 2;
    int bn0 = (tid & 31) << 2, bkp = tid >> 5;
    int wid = tid >> 5, lane = tid & 31;
    int wy = wid >> 2, wx = wid & 3;
    int g = lane >> 2, tg = lane & 3;

    float acc[4][4][4];
#pragma unroll
    for (int mi = 0; mi < 4; mi++)
#pragma unroll
        for (int ni = 0; ni < 4; ni++)
#pragma unroll
            for (int q = 0; q < 4; q++) acc[mi][ni][q] = 0.f;

    int nk = K >> 4;

    {
        int r = bm + ar;
        if (aPacked) {
            uint4 wa = make_uint4(0u,0u,0u,0u);
            if (r < M) wa = *(const uint4*)((const uint32_t*)A + (size_t)r*(K>>1) + aw);
            As[0][ar][aw+0] = wa.x; As[0][ar][aw+1] = wa.y;
            As[0][ar][aw+2] = wa.z; As[0][ar][aw+3] = wa.w;
        } else {
            float4 a0 = make_float4(0.f,0.f,0.f,0.f), a1 = a0;
            if (r < M) {
                a0 = *(const float4*)(A + (size_t)r*K + ak);
                a1 = *(const float4*)(A + (size_t)r*K + ak + 4);
            }
            As[0][ar][aw+0] = pkbf(a0.x, a0.y);
            As[0][ar][aw+1] = pkbf(a0.z, a0.w);
            As[0][ar][aw+2] = pkbf(a1.x, a1.y);
            As[0][ar][aw+3] = pkbf(a1.z, a1.w);
        }
        float4 b0 = *(const float4*)(B + (size_t)(2*bkp  )*N + bn + bn0);
        float4 b1 = *(const float4*)(B + (size_t)(2*bkp+1)*N + bn + bn0);
        Bs[0][bn0+0][bkp] = pkbf(b0.x, b1.x);
        Bs[0][bn0+1][bkp] = pkbf(b0.y, b1.y);
        Bs[0][bn0+2][bkp] = pkbf(b0.z, b1.z);
        Bs[0][bn0+3][bkp] = pkbf(b0.w, b1.w);
    }
    __syncthreads();

    int buf = 0;
    for (int kt = 0; kt < nk; kt++) {
        float4 a0, a1, b0, b1;
        uint4 wa;
        bool pf = (kt + 1 < nk);
        if (pf) {
            int k0 = (kt + 1) << 4;
            int r = bm + ar;
            if (aPacked) {
                wa = make_uint4(0u,0u,0u,0u);
                if (r < M) wa = *(const uint4*)((const uint32_t*)A + (size_t)r*(K>>1) + (k0>>1) + aw);
            } else {
                a0 = make_float4(0.f,0.f,0.f,0.f); a1 = a0;
                if (r < M) {
                    a0 = *(const float4*)(A + (size_t)r*K + k0 + ak);
                    a1 = *(const float4*)(A + (size_t)r*K + k0 + ak + 4);
                }
            }
            b0 = *(const float4*)(B + (size_t)(k0 + 2*bkp  )*N + bn + bn0);
            b1 = *(const float4*)(B + (size_t)(k0 + 2*bkp+1)*N + bn + bn0);
        }
        uint32_t af[4][4];
#pragma unroll
        for (int mi = 0; mi < 4; mi++) {
            int r0 = wy*64 + mi*16;
            af[mi][0] = As[buf][r0 + g    ][tg];
            af[mi][1] = As[buf][r0 + g + 8][tg];
            af[mi][2] = As[buf][r0 + g    ][tg + 4];
            af[mi][3] = As[buf][r0 + g + 8][tg + 4];
        }
        uint32_t bfr[4][2];
#pragma unroll
        for (int ni = 0; ni < 4; ni++) {
            int c0 = wx*32 + ni*8;
            bfr[ni][0] = Bs[buf][c0 + g][tg];
            bfr[ni][1] = Bs[buf][c0 + g][tg + 4];
        }
#pragma unroll
        for (int mi = 0; mi < 4; mi++)
#pragma unroll
            for (int ni = 0; ni < 4; ni++)
                mma_bf16(acc[mi][ni], af[mi], bfr[ni]);

        if (pf) {
            int nb = buf ^ 1;
            if (aPacked) {
                As[nb][ar][aw+0] = wa.x; As[nb][ar][aw+1] = wa.y;
                As[nb][ar][aw+2] = wa.z; As[nb][ar][aw+3] = wa.w;
            } else {
                As[nb][ar][aw+0] = pkbf(a0.x, a0.y);
                As[nb][ar][aw+1] = pkbf(a0.z, a0.w);
                As[nb][ar][aw+2] = pkbf(a1.x, a1.y);
                As[nb][ar][aw+3] = pkbf(a1.z, a1.w);
            }
            Bs[nb][bn0+0][bkp] = pkbf(b0.x, b1.x);
            Bs[nb][bn0+1][bkp] = pkbf(b0.y, b1.y);
            Bs[nb][bn0+2][bkp] = pkbf(b0.z, b1.z);
            Bs[nb][bn0+3][bkp] = pkbf(b0.w, b1.w);
        }
        __syncthreads();
        buf ^= 1;
    }

#pragma unroll
    for (int mi = 0; mi < 4; mi++) {
#pragma unroll
        for (int half = 0; half < 2; half++) {
            int r = bm + wy*64 + mi*16 + g + half*8;
            if (r >= M) continue;
#pragma unroll
            for (int ni = 0; ni < 4; ni++) {
                int c = bn + wx*32 + ni*8 + 2*tg;
                float v0 = acc[mi][ni][half*2+0] + (bias ? bias[c]   : 0.f);
                float v1 = acc[mi][ni][half*2+1] + (bias ? bias[c+1] : 0.f);
                if (act == 1) { v0 = fmaxf(v0, 0.f); v1 = fmaxf(v1, 0.f); }
                if (act == 2) {
                    int rr = r - PADT;
                    if (rr >= 0) {
                        float2* p = (float2*)(C + (size_t)rr*N + c);
                        float2 cur = *p;
                        cur.x += v0; cur.y += v1;
                        *p = cur;
                    }
                } else if (act == 4) {
                    ((uint32_t*)C)[(size_t)r*(N >> 1) + (c >> 1)] = pkbf(v0, v1);
                } else {
                    *(float2*)(C + (size_t)r*N + c) = make_float2(v0, v1);
                }
            }
        }
    }
}

// ==================== bf16 pinv GEMM: C = sc*(A @ (cI*I + eB*B)), 256x256x256 ====================
__global__ __launch_bounds__(256) void bf16pinv_k(
    const float* __restrict__ A, const float* __restrict__ B,
    float* __restrict__ C, size_t sAB, float cI, float eB, float sc)
{
    __shared__ uint32_t As[2][128][12];
    __shared__ uint32_t Bs[2][128][12];
    const int N = 256, K = 256;
    A += (size_t)blockIdx.z * sAB;
    B += (size_t)blockIdx.z * sAB;
    C += (size_t)blockIdx.z * sAB;
    int bm = blockIdx.y * 128, bn = blockIdx.x * 128;
    int tid = threadIdx.x;
    int ar = tid >> 1, ak = (tid & 1) << 3;
    int aw = (tid & 1) << 2;
    int bn0 = (tid & 31) << 2, bkp = tid >> 5;
    int wid = tid >> 5, lane = tid & 31;
    int wy = wid >> 2, wx = wid & 3;
    int g = lane >> 2, tg = lane & 3;

    float acc[4][4][4];
#pragma unroll
    for (int mi = 0; mi < 4; mi++)
#pragma unroll
        for (int ni = 0; ni < 4; ni++)
#pragma unroll
            for (int q = 0; q < 4; q++) acc[mi][ni][q] = 0.f;

    int col0 = bn + bn0;
    {
        int r = bm + ar;
        float4 a0 = *(const float4*)(A + (size_t)r*K + ak);
        float4 a1 = *(const float4*)(A + (size_t)r*K + ak + 4);
        As[0][ar][aw+0] = pkbf(a0.x, a0.y);
        As[0][ar][aw+1] = pkbf(a0.z, a0.w);
        As[0][ar][aw+2] = pkbf(a1.x, a1.y);
        As[0][ar][aw+3] = pkbf(a1.z, a1.w);
        int kr0 = 2*bkp, kr1 = kr0 + 1;
        float4 b0 = *(const float4*)(B + (size_t)kr0*N + col0);
        float4 b1 = *(const float4*)(B + (size_t)kr1*N + col0);
        float u0 = eB*b0.x + ((kr0 == col0    ) ? cI : 0.f);
        float u1 = eB*b0.y + ((kr0 == col0 + 1) ? cI : 0.f);
        float u2 = eB*b0.z + ((kr0 == col0 + 2) ? cI : 0.f);
        float u3 = eB*b0.w + ((kr0 == col0 + 3) ? cI : 0.f);
        float v0 = eB*b1.x + ((kr1 == col0    ) ? cI : 0.f);
        float v1 = eB*b1.y + ((kr1 == col0 + 1) ? cI : 0.f);
        float v2 = eB*b1.z + ((kr1 == col0 + 2) ? cI : 0.f);
        float v3 = eB*b1.w + ((kr1 == col0 + 3) ? cI : 0.f);
        Bs[0][bn0+0][bkp] = pkbf(u0, v0);
        Bs[0][bn0+1][bkp] = pkbf(u1, v1);
        Bs[0][bn0+2][bkp] = pkbf(u2, v2);
        Bs[0][bn0+3][bkp] = pkbf(u3, v3);
    }
    __syncthreads();

    int buf = 0;
    for (int kt = 0; kt < 16; kt++) {
        float4 a0, a1, b0, b1;
        int kr0 = 0;
        bool pf = (kt + 1 < 16);
        if (pf) {
            int k0 = (kt + 1) << 4;
            int r = bm + ar;
            a0 = *(const float4*)(A + (size_t)r*K + k0 + ak);
            a1 = *(const float4*)(A + (size_t)r*K + k0 + ak + 4);
            kr0 = k0 + 2*bkp;
            b0 = *(const float4*)(B + (size_t)kr0*N + col0);
            b1 = *(const float4*)(B + (size_t)(kr0+1)*N + col0);
        }
        uint32_t af[4][4];
#pragma unroll
        for (int mi = 0; mi < 4; mi++) {
            int r0 = wy*64 + mi*16;
            af[mi][0] = As[buf][r0 + g    ][tg];
            af[mi][1] = As[buf][r0 + g + 8][tg];
            af[mi][2] = As[buf][r0 + g    ][tg + 4];
            af[mi][3] = As[buf][r0 + g + 8][tg + 4];
        }
        uint32_t bfr[4][2];
#pragma unroll
        for (int ni = 0; ni < 4; ni++) {
            int c0 = wx*32 + ni*8;
            bfr[ni][0] = Bs[buf][c0 + g][tg];
            bfr[ni][1] = Bs[buf][c0 + g][tg + 4];
        }
#pragma unroll
        for (int mi = 0; mi < 4; mi++)
#pragma unroll
            for (int ni = 0; ni < 4; ni++)
                mma_bf16(acc[mi][ni], af[mi], bfr[ni]);

        if (pf) {
            int nb = buf ^ 1;
            int kr1 = kr0 + 1;
            As[nb][ar][aw+0] = pkbf(a0.x, a0.y);
            As[nb][ar][aw+1] = pkbf(a0.z, a0.w);
            As[nb][ar][aw+2] = pkbf(a1.x, a1.y);
            As[nb][ar][aw+3] = pkbf(a1.z, a1.w);
            float u0 = eB*b0.x + ((kr0 == col0    ) ? cI : 0.f);
            float u1 = eB*b0.y + ((kr0 == col0 + 1) ? cI : 0.f);
            float u2 = eB*b0.z + ((kr0 == col0 + 2) ? cI : 0.f);
            float u3 = eB*b0.w + ((kr0 == col0 + 3) ? cI : 0.f);
            float v0 = eB*b1.x + ((kr1 == col0    ) ? cI : 0.f);
            float v1 = eB*b1.y + ((kr1 == col0 + 1) ? cI : 0.f);
            float v2 = eB*b1.z + ((kr1 == col0 + 2) ? cI : 0.f);
            float v3 = eB*b1.w + ((kr1 == col0 + 3) ? cI : 0.f);
            Bs[nb][bn0+0][bkp] = pkbf(u0, v0);
            Bs[nb][bn0+1][bkp] = pkbf(u1, v1);
            Bs[nb][bn0+2][bkp] = pkbf(u2, v2);
            Bs[nb][bn0+3][bkp] = pkbf(u3, v3);
        }
        __syncthreads();
        buf ^= 1;
    }

#pragma unroll
    for (int mi = 0; mi < 4; mi++) {
#pragma unroll
        for (int half = 0; half < 2; half++) {
            int r = bm + wy*64 + mi*16 + g + half*8;
#pragma unroll
            for (int ni = 0; ni < 4; ni++) {
                int c = bn + wx*32 + ni*8 + 2*tg;
                *(float2*)(C + (size_t)r*N + c) =
                    make_float2(sc*acc[mi][ni][half*2+0], sc*acc[mi][ni][half*2+1]);
            }
        }
    }
}

// ==================== tf32 tensor-core GEMM (pinv polish), 128x128x8 ====================
__global__ __launch_bounds__(256) void tf32gemm_k(
    const float* __restrict__ A, const float* __restrict__ B,
    float* __restrict__ C, int Kd, size_t sAB,
    float cI, float eB, float sc)
{
    __shared__ uint32_t As[2][8][136];
    __shared__ uint32_t Bs[2][8][136];
    A += (size_t)blockIdx.z * sAB;
    B += (size_t)blockIdx.z * sAB;
    C += (size_t)blockIdx.z * sAB;
    const int N = 256;
    int bm = blockIdx.y * 128, bn = blockIdx.x * 128;
    int tid = threadIdx.x;
    int arow = tid >> 1, acol = (tid & 1) << 2;
    int brow = tid >> 5, bcol = (tid & 31) << 2;
    int wid = tid >> 5, lane = tid & 31;
    int wy = wid >> 2, wx = wid & 3;
    int g = lane >> 2, tg = lane & 3;

    float acc[4][4][4];
#pragma unroll
    for (int mi = 0; mi < 4; mi++)
#pragma unroll
        for (int ni = 0; ni < 4; ni++)
#pragma unroll
            for (int q = 0; q < 4; q++) acc[mi][ni][q] = 0.f;

    int nk = Kd >> 3;
    int col0 = bn + bcol;

    {
        float4 va = *(const float4*)(A + (size_t)(bm + arow)*Kd + acol);
        As[0][acol+0][arow] = f2tf32(va.x);
        As[0][acol+1][arow] = f2tf32(va.y);
        As[0][acol+2][arow] = f2tf32(va.z);
        As[0][acol+3][arow] = f2tf32(va.w);
        float4 vb = *(const float4*)(B + (size_t)brow*N + col0);
        float e0 = eB*vb.x, e1 = eB*vb.y, e2 = eB*vb.z, e3 = eB*vb.w;
        if (brow == col0    ) e0 += cI;
        if (brow == col0 + 1) e1 += cI;
        if (brow == col0 + 2) e2 += cI;
        if (brow == col0 + 3) e3 += cI;
        Bs[0][brow][bcol  ] = f2tf32(e0);
        Bs[0][brow][bcol+1] = f2tf32(e1);
        Bs[0][brow][bcol+2] = f2tf32(e2);
        Bs[0][brow][bcol+3] = f2tf32(e3);
    }
    __syncthreads();

    int buf = 0;
    for (int kt = 0; kt < nk; kt++) {
        float4 va, vb;
        bool pf = (kt + 1 < nk);
        if (pf) {
            int k0 = (kt + 1) << 3;
            va = *(const float4*)(A + (size_t)(bm + arow)*Kd + k0 + acol);
            vb = *(const float4*)(B + (size_t)(k0 + brow)*N + col0);
        }
        uint32_t af[4][4];
#pragma unroll
        for (int mi = 0; mi < 4; mi++) {
            int r0 = wy*64 + mi*16;
            af[mi][0] = As[buf][tg  ][r0 + g];
            af[mi][1] = As[buf][tg  ][r0 + g + 8];
            af[mi][2] = As[buf][tg+4][r0 + g];
            af[mi][3] = As[buf][tg+4][r0 + g + 8];
        }
        uint32_t bfr[4][2];
#pragma unroll
        for (int ni = 0; ni < 4; ni++) {
            int c0 = wx*32 + ni*8;
            bfr[ni][0] = Bs[buf][tg  ][c0 + g];
            bfr[ni][1] = Bs[buf][tg+4][c0 + g];
        }
#pragma unroll
        for (int mi = 0; mi < 4; mi++)
#pragma unroll
            for (int ni = 0; ni < 4; ni++)
                mma_tf32(acc[mi][ni], af[mi], bfr[ni]);

        if (pf) {
            int nb = buf ^ 1;
            int kr = ((kt + 1) << 3) + brow;
            As[nb][acol+0][arow] = f2tf32(va.x);
            As[nb][acol+1][arow] = f2tf32(va.y);
            As[nb][acol+2][arow] = f2tf32(va.z);
            As[nb][acol+3][arow] = f2tf32(va.w);
            float e0 = eB*vb.x, e1 = eB*vb.y, e2 = eB*vb.z, e3 = eB*vb.w;
            if (kr == col0    ) e0 += cI;
            if (kr == col0 + 1) e1 += cI;
            if (kr == col0 + 2) e2 += cI;
            if (kr == col0 + 3) e3 += cI;
            Bs[nb][brow][bcol  ] = f2tf32(e0);
            Bs[nb][brow][bcol+1] = f2tf32(e1);
            Bs[nb][brow][bcol+2] = f2tf32(e2);
            Bs[nb][brow][bcol+3] = f2tf32(e3);
        }
        __syncthreads();
        buf ^= 1;
    }

#pragma unroll
    for (int mi = 0; mi < 4; mi++) {
#pragma unroll
        for (int half = 0; half < 2; half++) {
            int r = bm + wy*64 + mi*16 + g + half*8;
#pragma unroll
            for (int ni = 0; ni < 4; ni++) {
                int c = bn + wx*32 + ni*8 + 2*tg;
                *(float2*)(C + (size_t)r*N + c) =
                    make_float2(sc*acc[mi][ni][half*2+0], sc*acc[mi][ni][half*2+1]);
            }
        }
    }
}

// ==================== fused attention (bf16), 64-wide chunks ====================
#define SW_QS 0
#define SW_KS 4608
#define SW_VS 6912
#define SW_PS 9216
#define SW_RS 13824
#define SM_FUSED_BYTES ((13824 + 4608 + 128)*4)

__global__ __launch_bounds__(256) void a3_fused_k() {
    extern __shared__ uint32_t sm[];
    uint32_t* qs = sm + SW_QS;
    uint32_t* Ks = sm + SW_KS;
    uint32_t* Vs = sm + SW_VS;
    uint32_t* Ps = sm + SW_PS;
    float* rsm = (float*)(sm + SW_RS);

    int split = blockIdx.x;
    int bm = blockIdx.y * 128;
    int z = blockIdx.z; int zb = z / NH, zh = z % NH;
    int tid = threadIdx.x;
    int wid = tid >> 5, lane = tid & 31;
    int wy = wid >> 2, wx = wid & 3;
    int wy2 = wid >> 1, wx2 = wid & 1;
    int g = lane >> 2, tg = lane & 3;

    if (tid < 128) rsm[tid] = 0.f;

    for (int i = tid; i < 128*16; i += 256) {
        int row = i >> 4, f4 = (i & 15) << 2;
        float4 v = *(const float4*)(d_ql + ((size_t)(z*ML + bm + row))*DH + f4);
        qs[row*36 + (f4>>1)    ] = pkbf(v.x, v.y);
        qs[row*36 + (f4>>1) + 1] = pkbf(v.z, v.w);
    }

    float acc_o[2][4][4];
#pragma unroll
    for (int a = 0; a < 2; a++)
#pragma unroll
        for (int b = 0; b < 4; b++)
#pragma unroll
            for (int q = 0; q < 4; q++) acc_o[a][b][q] = 0.f;
    float rs_loc[8];
#pragma unroll
    for (int a = 0; a < 8; a++) rs_loc[a] = 0.f;

    for (int ci = 0; ci < 12; ci++) {
        int c0 = split*768 + ci*64;
        for (int i = tid; i < 64*8; i += 256) {
            int tok = i >> 3, p4 = (i & 7) << 2;
            uint4 w = *(const uint4*)(d_qkvh + ((size_t)(zb*NP + c0 + tok))*768 + 256 + zh*32 + p4);
            Ks[tok*36 + p4+0] = w.x;
            Ks[tok*36 + p4+1] = w.y;
            Ks[tok*36 + p4+2] = w.z;
            Ks[tok*36 + p4+3] = w.w;
        }
        for (int i = tid; i < 32*8; i += 256) {
            int tp = i >> 3, p4 = (i & 7) << 2;
            const uint32_t* vb0 = d_qkvh + ((size_t)(zb*NP + c0 + 2*tp))*768 + 512 + zh*32 + p4;
            uint4 wa = *(const uint4*)vb0;
            uint4 wb = *(const uint4*)(vb0 + 768);
            Vs[(2*(p4+0)  )*36 + tp] = __byte_perm(wa.x, wb.x, 0x5410);
            Vs[(2*(p4+0)+1)*36 + tp] = __byte_perm(wa.x, wb.x, 0x7632);
            Vs[(2*(p4+1)  )*36 + tp] = __byte_perm(wa.y, wb.y, 0x5410);
            Vs[(2*(p4+1)+1)*36 + tp] = __byte_perm(wa.y, wb.y, 0x7632);
            Vs[(2*(p4+2)  )*36 + tp] = __byte_perm(wa.z, wb.z, 0x5410);
            Vs[(2*(p4+2)+1)*36 + tp] = __byte_perm(wa.z, wb.z, 0x7632);
            Vs[(2*(p4+3)  )*36 + tp] = __byte_perm(wa.w, wb.w, 0x5410);
            Vs[(2*(p4+3)+1)*36 + tp] = __byte_perm(wa.w, wb.w, 0x7632);
        }
        __syncthreads();

        float acc_s[4][2][4];
#pragma unroll
        for (int a = 0; a < 4; a++)
#pragma unroll
            for (int b = 0; b < 2; b++)
#pragma unroll
                for (int q = 0; q < 4; q++) acc_s[a][b][q] = 0.f;

#pragma unroll
        for (int kk = 0; kk < 4; kk++) {
            uint32_t af[4][4], bfr[2][2];
#pragma unroll
            for (int mi = 0; mi < 4; mi++) {
                int r0 = wy*64 + mi*16;
                af[mi][0] = qs[(r0 + g    )*36 + kk*8 + tg];
                af[mi][1] = qs[(r0 + g + 8)*36 + kk*8 + tg];
                af[mi][2] = qs[(r0 + g    )*36 + kk*8 + tg + 4];
                af[mi][3] = qs[(r0 + g + 8)*36 + kk*8 + tg + 4];
            }
#pragma unroll
            for (int ni = 0; ni < 2; ni++) {
                int cw = wx*16 + ni*8;
                bfr[ni][0] = Ks[(cw + g)*36 + kk*8 + tg];
                bfr[ni][1] = Ks[(cw + g)*36 + kk*8 + tg + 4];
            }
#pragma unroll
            for (int mi = 0; mi < 4; mi++)
#pragma unroll
                for (int ni = 0; ni < 2; ni++)
                    mma_bf16(acc_s[mi][ni], af[mi], bfr[ni]);
        }

#pragma unroll
        for (int mi = 0; mi < 4; mi++)
#pragma unroll
            for (int half = 0; half < 2; half++) {
                int rl = wy*64 + mi*16 + half*8 + g;
                float ra = 0.f;
#pragma unroll
                for (int ni = 0; ni < 2; ni++) {
                    int cp = wx*8 + ni*4 + tg;
                    float v0 = __expf(acc_s[mi][ni][half*2+0]);
                    float v1 = __expf(acc_s[mi][ni][half*2+1]);
                    Ps[rl*36 + cp] = pkbf(v0, v1);
                    ra += v0 + v1;
                }
                rs_loc[mi*2 + half] += ra;
            }
        __syncthreads();

#pragma unroll
        for (int kk = 0; kk < 4; kk++) {
            uint32_t af2[2][4], bf2[4][2];
#pragma unroll
            for (int mi2 = 0; mi2 < 2; mi2++) {
                int m0 = wy2*32 + mi2*16;
                af2[mi2][0] = Ps[(m0 + g    )*36 + kk*8 + tg];
                af2[mi2][1] = Ps[(m0 + g + 8)*36 + kk*8 + tg];
                af2[mi2][2] = Ps[(m0 + g    )*36 + kk*8 + tg + 4];
                af2[mi2][3] = Ps[(m0 + g + 8)*36 + kk*8 + tg + 4];
            }
#pragma unroll
            for (int ni2 = 0; ni2 < 4; ni2++) {
                int cw = wx2*32 + ni2*8;
                bf2[ni2][0] = Vs[(cw + g)*36 + kk*8 + tg];
                bf2[ni2][1] = Vs[(cw + g)*36 + kk*8 + tg + 4];
            }
#pragma unroll
            for (int mi2 = 0; mi2 < 2; mi2++)
#pragma unroll
                for (int ni2 = 0; ni2 < 4; ni2++)
                    mma_bf16(acc_o[mi2][ni2], af2[mi2], bf2[ni2]);
        }
        __syncthreads();
    }

#pragma unroll
    for (int j2 = 0; j2 < 8; j2++) {
        int rl = wy*64 + (j2>>1)*16 + (j2&1)*8 + g;
        atomicAdd(&rsm[rl], rs_loc[j2]);
    }
    __syncthreads();
    if (tid < 128) atomicAdd(d_rs + (size_t)z*ML + bm + tid, rsm[tid]);
#pragma unroll
    for (int mi2 = 0; mi2 < 2; mi2++)
#pragma unroll
        for (int half = 0; half < 2; half++) {
            int m = wy2*32 + mi2*16 + half*8 + g;
#pragma unroll
            for (int ni2 = 0; ni2 < 4; ni2++) {
                int cc = wx2*32 + ni2*8 + 2*tg;
                float* dst = d_a3v + ((size_t)(z*ML + bm + m))*DH + cc;
                atomicAdd(dst,     acc_o[mi2][ni2][half*2+0]);
                atomicAdd(dst + 1, acc_o[mi2][ni2][half*2+1]);
            }
        }
}

__global__ __launch_bounds__(256) void a1_fused_k() {
    extern __shared__ uint32_t sm[];
    uint32_t* qs = sm + SW_QS;
    uint32_t* Ks = sm + SW_KS;
    uint32_t* Vs = sm + SW_VS;
    uint32_t* Ps = sm + SW_PS;
    float* rsm = (float*)(sm + SW_RS);

    int bm = blockIdx.x * 128;
    int z = blockIdx.y; int zb = z / NH, zh = z % NH;
    int tid = threadIdx.x;
    int wid = tid >> 5, lane = tid & 31;
    int wy = wid >> 2, wx = wid & 3;
    int wy2 = wid >> 1, wx2 = wid & 1;
    int g = lane >> 2, tg = lane & 3;

    const uint32_t EIGHTH = 0x3E003E00u;

    if (tid < 128) rsm[tid] = 0.f;

    for (int i = tid; i < 128*8; i += 256) {
        int row = i >> 3, p4 = (i & 7) << 2;
        uint4 w = *(const uint4*)(d_qkvh + ((size_t)(zb*NP + bm + row))*768 + zh*32 + p4);
        qs[row*36 + p4+0] = mulbf2(w.x, EIGHTH);
        qs[row*36 + p4+1] = mulbf2(w.y, EIGHTH);
        qs[row*36 + p4+2] = mulbf2(w.z, EIGHTH);
        qs[row*36 + p4+3] = mulbf2(w.w, EIGHTH);
    }

    float acc_o[2][4][4];
#pragma unroll
    for (int a = 0; a < 2; a++)
#pragma unroll
        for (int b = 0; b < 4; b++)
#pragma unroll
            for (int q = 0; q < 4; q++) acc_o[a][b][q] = 0.f;
    float rs_loc[8];
#pragma unroll
    for (int a = 0; a < 8; a++) rs_loc[a] = 0.f;

    for (int lc = 0; lc < 4; lc++) {
        int base = lc*64;
        for (int i = tid; i < 64*16; i += 256) {
            int lm = i >> 4, f4 = (i & 15) << 2;
            float4 kv = *(const float4*)(d_kl + ((size_t)(z*ML + base + lm))*DH + f4);
            Ks[lm*36 + (f4>>1)    ] = pkbf(kv.x, kv.y);
            Ks[lm*36 + (f4>>1) + 1] = pkbf(kv.z, kv.w);
        }
        for (int i = tid; i < 32*16; i += 256) {
            int lp = i >> 4, f4 = (i & 15) << 2;
            const float* wb0 = d_w2 + ((size_t)(z*ML + base + 2*lp))*DH + f4;
            float4 w0 = *(const float4*)wb0;
            float4 w1 = *(const float4*)(wb0 + DH);
            Vs[(f4+0)*36 + lp] = pkbf(w0.x, w1.x);
            Vs[(f4+1)*36 + lp] = pkbf(w0.y, w1.y);
            Vs[(f4+2)*36 + lp] = pkbf(w0.z, w1.z);
            Vs[(f4+3)*36 + lp] = pkbf(w0.w, w1.w);
        }
        __syncthreads();

        float acc_s[4][2][4];
#pragma unroll
        for (int a = 0; a < 4; a++)
#pragma unroll
            for (int b = 0; b < 2; b++)
#pragma unroll
                for (int q = 0; q < 4; q++) acc_s[a][b][q] = 0.f;

#pragma unroll
        for (int kk = 0; kk < 4; kk++) {
            uint32_t af[4][4], bfr[2][2];
#pragma unroll
            for (int mi = 0; mi < 4; mi++) {
                int r0 = wy*64 + mi*16;
                af[mi][0] = qs[(r0 + g    )*36 + kk*8 + tg];
                af[mi][1] = qs[(r0 + g + 8)*36 + kk*8 + tg];
                af[mi][2] = qs[(r0 + g    )*36 + kk*8 + tg + 4];
                af[mi][3] = qs[(r0 + g + 8)*36 + kk*8 + tg + 4];
            }
#pragma unroll
            for (int ni = 0; ni < 2; ni++) {
                int cw = wx*16 + ni*8;
                bfr[ni][0] = Ks[(cw + g)*36 + kk*8 + tg];
                bfr[ni][1] = Ks[(cw + g)*36 + kk*8 + tg + 4];
            }
#pragma unroll
            for (int mi = 0; mi < 4; mi++)
#pragma unroll
                for (int ni = 0; ni < 2; ni++)
                    mma_bf16(acc_s[mi][ni], af[mi], bfr[ni]);
        }

#pragma unroll
        for (int mi = 0; mi < 4; mi++)
#pragma unroll
            for (int half = 0; half < 2; half++) {
                int rl = wy*64 + mi*16 + half*8 + g;
                float ra = 0.f;
#pragma unroll
                for (int ni = 0; ni < 2; ni++) {
                    int cp = wx*8 + ni*4 + tg;
                    float v0 = __expf(acc_s[mi][ni][half*2+0]);
                    float v1 = __expf(acc_s[mi][ni][half*2+1]);
                    Ps[rl*36 + cp] = pkbf(v0, v1);
                    ra += v0 + v1;
                }
                rs_loc[mi*2 + half] += ra;
            }
        __syncthreads();

#pragma unroll
        for (int kk = 0; kk < 4; kk++) {
            uint32_t af2[2][4], bf2[4][2];
#pragma unroll
            for (int mi2 = 0; mi2 < 2; mi2++) {
                int m0 = wy2*32 + mi2*16;
                af2[mi2][0] = Ps[(m0 + g    )*36 + kk*8 + tg];
                af2[mi2][1] = Ps[(m0 + g + 8)*36 + kk*8 + tg];
                af2[mi2][2] = Ps[(m0 + g    )*36 + kk*8 + tg + 4];
                af2[mi2][3] = Ps[(m0 + g + 8)*36 + kk*8 + tg + 4];
            }
#pragma unroll
            for (int ni2 = 0; ni2 < 4; ni2++) {
                int cw = wx2*32 + ni2*8;
                bf2[ni2][0] = Vs[(cw + g)*36 + kk*8 + tg];
                bf2[ni2][1] = Vs[(cw + g)*36 + kk*8 + tg + 4];
            }
#pragma unroll
            for (int mi2 = 0; mi2 < 2; mi2++)
#pragma unroll
                for (int ni2 = 0; ni2 < 4; ni2++)
                    mma_bf16(acc_o[mi2][ni2], af2[mi2], bf2[ni2]);
        }
        __syncthreads();
    }

#pragma unroll
    for (int j2 = 0; j2 < 8; j2++) {
        int rl = wy*64 + (j2>>1)*16 + (j2&1)*8 + g;
        atomicAdd(&rsm[rl], rs_loc[j2]);
    }
    __syncthreads();
#pragma unroll
    for (int mi2 = 0; mi2 < 2; mi2++)
#pragma unroll
        for (int half = 0; half < 2; half++) {
            int m = wy2*32 + mi2*16 + half*8 + g;
            float inv = 1.f / rsm[m];
#pragma unroll
            for (int ni2 = 0; ni2 < 4; ni2++) {
                int cc = wx2*32 + ni2*8 + 2*tg;
                d_attnh[(size_t)(zb*NP + bm + m)*256 + ((zh*64 + cc) >> 1)] =
                    pkbf(acc_o[mi2][ni2][half*2+0]*inv, acc_o[mi2][ni2][half*2+1]*inv);
            }
        }
}

// -------------------- small 64-tile batched GEMM (fp32) with optional B row-scale --------------------
__global__ __launch_bounds__(256) void bgemm_epi(
    const float* __restrict__ A, const float* __restrict__ Bm, float* __restrict__ C,
    int Md, int Nd, int Kd, float cI, float eB, float s, const float* __restrict__ rsc)
{
    __shared__ float As[16][64];
    __shared__ float Bs[16][64];
    A  += (size_t)blockIdx.z * Md * Kd;
    Bm += (size_t)blockIdx.z * Kd * Nd;
    C  += (size_t)blockIdx.z * Md * Nd;
    const float* rscz = rsc ? rsc + (size_t)blockIdx.z * Kd : nullptr;
    int bm = blockIdx.y * 64, bn = blockIdx.x * 64;
    int tid = threadIdx.x;
    int la_r = tid >> 2, la_c = (tid & 3) << 2;
    int lb_r = tid >> 4, lb_c = (tid & 15) << 2;
    int ty = tid >> 4, tx = tid & 15;
    float acc[4][4];
#pragma unroll
    for (int i = 0; i < 4; i++)
#pragma unroll
        for (int j = 0; j < 4; j++) acc[i][j] = 0.f;

    for (int k0 = 0; k0 < Kd; k0 += 16) {
        float4 av = *(const float4*)(A + (size_t)(bm + la_r)*Kd + k0 + la_c);
        As[la_c  ][la_r] = av.x;
        As[la_c+1][la_r] = av.y;
        As[la_c+2][la_r] = av.z;
        As[la_c+3][la_r] = av.w;
        int kr = k0 + lb_r;
        float4 bv = *(const float4*)(Bm + (size_t)kr*Nd + bn + lb_c);
        float rsv = rscz ? (1.f / rscz[kr]) : 1.f;
        float e0 = eB*rsv*bv.x, e1 = eB*rsv*bv.y, e2 = eB*rsv*bv.z, e3 = eB*rsv*bv.w;
        int c0 = bn + lb_c;
        if (kr == c0    ) e0 += cI;
        if (kr == c0 + 1) e1 += cI;
        if (kr == c0 + 2) e2 += cI;
        if (kr == c0 + 3) e3 += cI;
        Bs[lb_r][lb_c  ] = e0;
        Bs[lb_r][lb_c+1] = e1;
        Bs[lb_r][lb_c+2] = e2;
        Bs[lb_r][lb_c+3] = e3;
        __syncthreads();
#pragma unroll
        for (int kk = 0; kk < 16; kk++) {
            float a0 = As[kk][ty*4+0], a1 = As[kk][ty*4+1], a2 = As[kk][ty*4+2], a3 = As[kk][ty*4+3];
            float b0 = Bs[kk][tx*4+0], b1 = Bs[kk][tx*4+1], b2 = Bs[kk][tx*4+2], b3 = Bs[kk][tx*4+3];
            acc[0][0]+=a0*b0; acc[0][1]+=a0*b1; acc[0][2]+=a0*b2; acc[0][3]+=a0*b3;
            acc[1][0]+=a1*b0; acc[1][1]+=a1*b1; acc[1][2]+=a1*b2; acc[1][3]+=a1*b3;
            acc[2][0]+=a2*b0; acc[2][1]+=a2*b1; acc[2][2]+=a2*b2; acc[2][3]+=a2*b3;
            acc[3][0]+=a3*b0; acc[3][1]+=a3*b1; acc[3][2]+=a3*b2; acc[3][3]+=a3*b3;
        }
        __syncthreads();
    }
#pragma unroll
    for (int i = 0; i < 4; i++) {
        int r = bm + ty*4 + i;
#pragma unroll
        for (int j = 0; j < 4; j++) {
            int c = bn + tx*4 + j;
            C[(size_t)r*Nd + c] = s * acc[i][j];
        }
    }
}

// -------------------- misc small kernels --------------------
__global__ void fill_cls_k(const float* __restrict__ cls) {
    int i = blockIdx.x*256 + threadIdx.x;
    if (i < BB*EMBD) d_h[(size_t)(i/EMBD)*NT*EMBD + (i % EMBD)] = cls[i % EMBD];
}

__global__ void fill_wrap_k() {
    int i = blockIdx.x*256 + threadIdx.x;
    if (i >= BB*ADDW*EMBD) return;
    int c = i % EMBD; int r = i / EMBD; int j = r % ADDW; int b = r / ADDW;
    d_h[((size_t)(b*NT + 1 + N0 + j))*EMBD + c] = d_h[((size_t)(b*NT + 1 + j))*EMBD + c];
}

// copy cls row from d_h into d_h2 (layer-2 residual buffer)
__global__ void copy_cls_k() {
    int i = blockIdx.x*256 + threadIdx.x;
    if (i >= BB*EMBD) return;
    int b = i / EMBD, c = i % EMBD;
    d_h2[(size_t)b*NT*EMBD + c] = d_h[(size_t)b*NT*EMBD + c];
}

// layernorm: one warp per row, shuffle reductions, bf16x2-packed output; residual source h
__global__ __launch_bounds__(256) void ln_pad_k2(const float* __restrict__ h,
                                                 const float* __restrict__ g, const float* __restrict__ bp) {
    int tid = threadIdx.x, wid = tid >> 5, lane = tid & 31;
    int row = blockIdx.x*8 + wid;
    int b = row / NP, t = row % NP;
    uint32_t* out = d_xnh + (size_t)row*256;
    if (t < PADT) {
#pragma unroll
        for (int k = 0; k < 4; k++)
            *(uint2*)(out + k*64 + lane*2) = make_uint2(0u, 0u);
        return;
    }
    const float* x = h + ((size_t)b*NT + (t - PADT))*EMBD;
    float4 v[4];
    float s = 0.f;
#pragma unroll
    for (int k = 0; k < 4; k++) {
        v[k] = *(const float4*)(x + k*128 + lane*4);
        s += v[k].x + v[k].y + v[k].z + v[k].w;
    }
#pragma unroll
    for (int o = 16; o > 0; o >>= 1) s += __shfl_xor_sync(0xffffffffu, s, o);
    float mean = s * (1.f/512.f);
    float s2 = 0.f;
#pragma unroll
    for (int k = 0; k < 4; k++) {
        v[k].x -= mean; v[k].y -= mean; v[k].z -= mean; v[k].w -= mean;
        s2 += v[k].x*v[k].x + v[k].y*v[k].y + v[k].z*v[k].z + v[k].w*v[k].w;
    }
#pragma unroll
    for (int o = 16; o > 0; o >>= 1) s2 += __shfl_xor_sync(0xffffffffu, s2, o);
    float inv = rsqrtf(s2 * (1.f/512.f) + 1e-5f);
#pragma unroll
    for (int k = 0; k < 4; k++) {
        float4 gv = *(const float4*)(g  + k*128 + lane*4);
        float4 bv = *(const float4*)(bp + k*128 + lane*4);
        uint2 o2;
        o2.x = pkbf(v[k].x*inv*gv.x + bv.x, v[k].y*inv*gv.y + bv.y);
        o2.y = pkbf(v[k].z*inv*gv.z + bv.z, v[k].w*inv*gv.w + bv.w);
        *(uint2*)(out + k*64 + lane*2) = o2;
    }
}

__global__ void landmarks_k() {
    int blk = blockIdx.x; int bh = blk >> 8; int i = blk & 255;
    int d = threadIdx.x;
    int b = bh / NH, h = bh % NH;
    int p = d >> 1, hi = d & 1;
    const uint32_t* base = d_qkvh + ((size_t)(b*NP) + (size_t)i*LWIN)*768 + h*32 + p;
    float sq = 0.f, sk = 0.f;
#pragma unroll
    for (int j = 0; j < LWIN; j++) {
        uint32_t wq = base[(size_t)j*768];
        uint32_t wk = base[(size_t)j*768 + 256];
        sq += hi ? bhi(wq) : blo(wq);
        sk += hi ? bhi(wk) : blo(wk);
    }
    d_ql[((size_t)(bh*ML + i))*DH + d] = sq * (0.125f / LWIN);
    d_kl[((size_t)(bh*ML + i))*DH + d] = sk * (1.f   / LWIN);
}

__global__ __launch_bounds__(256) void a2_k() {
    int blk = blockIdx.x; int bh = blk >> 8; int i = blk & 255;
    int tid = threadIdx.x;
    __shared__ float sq[64];
    __shared__ float red[256];
    if (tid < 64) sq[tid] = d_ql[((size_t)(bh*ML + i))*DH + tid];
    __syncthreads();
    float s = dot64(sq, d_kl + ((size_t)(bh*ML + tid))*DH);
    red[tid] = s; __syncthreads();
    for (int o = 128; o > 0; o >>= 1) { if (tid < o) red[tid] = fmaxf(red[tid], red[tid+o]); __syncthreads(); }
    float m = red[0]; __syncthreads();
    float p = expf(s - m);
    red[tid] = p; __syncthreads();
    for (int o = 128; o > 0; o >>= 1) { if (tid < o) red[tid] += red[tid+o]; __syncthreads(); }
    float Z = red[0];
    d_a2[((size_t)bh << 16) + ((size_t)i << 8) + tid] = p / Z;
}

// per-bh max column sum, plain store (overwritten each layer, no reset needed)
__global__ __launch_bounds__(256) void a2_stats_k() {
    int bh = blockIdx.x; int tid = threadIdx.x;
    const float* a = d_a2 + ((size_t)bh << 16);
    float cs = 0.f;
    for (int i = 0; i < ML; i++) cs += a[(size_t)i*ML + tid];
    __shared__ float red[256];
    red[tid] = cs; __syncthreads();
    for (int o = 128; o > 0; o >>= 1) { if (tid < o) red[tid] = fmaxf(red[tid], red[tid+o]); __syncthreads(); }
    if (tid == 0) d_mxb[bh] = red[0];
}

__global__ void z_init_k() {
    __shared__ float denom_s;
    if (threadIdx.x == 0) {
        float m = d_mxb[0];
#pragma unroll
        for (int i = 1; i < BH; i++) m = fmaxf(m, d_mxb[i]);
        denom_s = m;
    }
    __syncthreads();
    float denom = denom_s;
    size_t idx = (size_t)blockIdx.x*256 + threadIdx.x;
    if (idx >= (size_t)BH*ML*ML) return;
    size_t bh = idx >> 16; size_t r = (idx >> 8) & 255; size_t c = idx & 255;
    d_z0[idx] = d_a2[(bh << 16) + (c << 8) + r] / denom;
}

// conv residual: V bf16 in, RMW on packed bf16 attn
__global__ __launch_bounds__(256) void conv_res_k(const float* __restrict__ w) {
    __shared__ float vs[160*64];
    __shared__ float ws[33];
    int blk = blockIdx.x;
    int strip = blk % 48; int bh = blk / 48; int h = bh % NH; int b = bh / NH;
    int t0 = strip * 128;
    int tid = threadIdx.x;
    if (tid < 33) ws[tid] = w[h*33 + tid];
    for (int i = tid; i < 160*16; i += 256) {
        int row = i >> 4, f4 = (i & 15) << 2;
        int t = t0 - 16 + row;
        float4 v = make_float4(0.f,0.f,0.f,0.f);
        if (t >= 0 && t < NP) {
            uint2 wv = *(const uint2*)(d_qkvh + ((size_t)(b*NP + t))*768 + 512 + h*32 + (f4 >> 1));
            v.x = blo(wv.x); v.y = bhi(wv.x); v.z = blo(wv.y); v.w = bhi(wv.y);
        }
        *(float4*)(vs + row*64 + f4) = v;
    }
    __syncthreads();
#pragma unroll
    for (int j = 0; j < 8; j++) {
        int o = tid + j*256;
        int row = o >> 4, f4 = (o & 15) << 2;
        float4 s = make_float4(0.f,0.f,0.f,0.f);
#pragma unroll
        for (int k = 0; k < 33; k++) {
            float4 v = *(const float4*)(vs + (row + k)*64 + f4);
            float wk = ws[k];
            s.x += v.x*wk; s.y += v.y*wk; s.z += v.z*wk; s.w += v.w*wk;
        }
        uint2* dst = (uint2*)(d_attnh + (size_t)(b*NP + t0 + row)*256 + ((h*64 + f4) >> 1));
        uint2 cur = *dst;
        cur.x = pkbf(blo(cur.x) + s.x, bhi(cur.x) + s.y);
        cur.y = pkbf(blo(cur.y) + s.z, bhi(cur.y) + s.w);
        *dst = cur;
    }
}

// combined PPEG weights
__global__ void wtrans_k(const float* __restrict__ w7, const float* __restrict__ w5,
                         const float* __restrict__ w3) {
    int i = blockIdx.x*256 + threadIdx.x;
    if (i >= 49*EMBD) return;
    int aq = i / EMBD, c = i % EMBD;
    int a = aq / 7, q = aq % 7;
    float v = w7[c*49 + aq];
    if (a >= 1 && a <= 5 && q >= 1 && q <= 5) v += w5[c*25 + (a-1)*5 + (q-1)];
    if (a >= 2 && a <= 4 && q >= 2 && q <= 4) v += w3[c*9  + (a-2)*3 + (q-2)];
    d_wct[i] = v;
}

// PPEG: row-tiled single 7x7 conv, reads d_h, writes DIRECTLY into d_h2 token rows
#define PP_SMEM_BYTES (7*84*32*4)
__global__ __launch_bounds__(256) void ppeg3_k(
    const float* __restrict__ b7, const float* __restrict__ b5, const float* __restrict__ b3)
{
    extern __shared__ float sb[];
    int cg = blockIdx.x;
    int i  = blockIdx.y;
    int b  = blockIdx.z;
    int tid = threadIdx.x;
    const float* hbase = d_h + ((size_t)(b*NT + 1))*EMBD + cg*32;
    for (int idx = tid; idx < 7*84*8; idx += 256) {
        int f4 = (idx & 7) << 2;
        int jj = (idx >> 3) % 84;
        int r  = idx / (84*8);
        int ii = i - 3 + r, px = jj - 3;
        float4 v = make_float4(0.f,0.f,0.f,0.f);
        if (ii >= 0 && ii < HW && px >= 0 && px < HW)
            v = *(const float4*)(hbase + (size_t)(ii*HW + px)*EMBD + f4);
        *(float4*)(sb + (r*84 + jj)*32 + f4) = v;
    }
    __syncthreads();
    int c = tid & 31, jgrp = tid >> 5;
    float wr[49];
#pragma unroll
    for (int t = 0; t < 49; t++) wr[t] = d_wct[t*EMBD + cg*32 + c];
    float bs = b7[cg*32 + c] + b5[cg*32 + c] + b3[cg*32 + c];
    for (int j = jgrp; j < HW; j += 8) {
        float s = sb[(3*84 + j + 3)*32 + c] + bs;
#pragma unroll
        for (int a = 0; a < 7; a++)
#pragma unroll
            for (int q = 0; q < 7; q++)
                s += sb[(a*84 + j + q)*32 + c] * wr[a*7 + q];
        d_h2[((size_t)(b*NT + 1) + i*HW + j)*EMBD + cg*32 + c] = s;
    }
}

__global__ __launch_bounds__(256) void head_k(
    const float* __restrict__ h,
    const float* __restrict__ g, const float* __restrict__ bp,
    const float* __restrict__ w, const float* __restrict__ bias, float* __restrict__ out)
{
    int b = blockIdx.x; int tid = threadIdx.x;
    __shared__ float xs[512];
    __shared__ float red[256];
    __shared__ float lg[4];
    const float* x = h + (size_t)b*NT*EMBD;
    float v0 = x[tid], v1 = x[tid+256];
    red[tid] = v0 + v1; __syncthreads();
    for (int o = 128; o > 0; o >>= 1) { if (tid < o) red[tid] += red[tid+o]; __syncthreads(); }
    float mean = red[0] * (1.f/512.f); __syncthreads();
    float e0 = v0 - mean, e1 = v1 - mean;
    red[tid] = e0*e0 + e1*e1; __syncthreads();
    for (int o = 128; o > 0; o >>= 1) { if (tid < o) red[tid] += red[tid+o]; __syncthreads(); }
    float inv = rsqrtf(red[0] * (1.f/512.f) + 1e-5f);
    xs[tid]     = e0*inv*g[tid]     + bp[tid];
    xs[tid+256] = e1*inv*g[tid+256] + bp[tid+256];
    __syncthreads();
    if (tid < 4) {
        float s = bias[tid];
        for (int k = 0; k < 512; k++) s += xs[k]*w[k*4 + tid];
        lg[tid] = s;
    }
    __syncthreads();
    if (tid == 0) {
        int best = 0; float bv = lg[0];
        for (int k = 1; k < 4; k++) if (lg[k] > bv) { bv = lg[k]; best = k; }
        float S = 1.f;
        for (int k = 0; k < 4; k++) {
            float hz = 1.f / (1.f + expf(-lg[k]));
            out[b*4 + k] = hz;
            S *= (1.f - hz);
            out[16 + b*4 + k] = S;
        }
        out[32 + b] = (float)best;
    }
}

// -------------------- host orchestration --------------------
static float* symaddr(const void* sym) { void* p = nullptr; cudaGetSymbolAddress(&p, sym); return (float*)p; }

static void attn_layer(float* hbuf,
                       const float* lng, const float* lnb, const float* qkvw,
                       const float* outw, const float* outb, const float* resw)
{
    float* xnhp  = symaddr(d_xnh);
    float* qkvp  = symaddr(d_qkvh);
    float* attnp = symaddr(d_attnh);
    float* a2p   = symaddr(d_a2);
    float* z0p   = symaddr(d_z0);
    float* z1p   = symaddr(d_z1);
    float* t0p   = symaddr(d_t0);
    float* t1p   = symaddr(d_t1);
    float* t2p   = symaddr(d_t2);
    float* a3vp  = symaddr(d_a3v);
    float* w2p   = symaddr(d_w2);
    float* rsp   = symaddr(d_rs);

    ln_pad_k2<<<BB*NP/8, 256>>>(hbuf, lng, lnb);
    bf16gemm_k<<<dim3(1536/128, NP/128, BB), 256>>>(
        xnhp, qkvw, nullptr, qkvp, NP, 1536, EMBD,
        (size_t)NP*256, (size_t)NP*768, 4, 1);
    landmarks_k<<<BH*ML, 64>>>();
    a2_k<<<BH*ML, 256>>>();
    a2_stats_k<<<BH, 256>>>();
    z_init_k<<<(BH*ML*ML + 255)/256, 256>>>();

    const size_t SB = (size_t)ML*ML;
    float* zin = z0p; float* zout = z1p;
    // iterations 0-3 in bf16 (Newton self-corrects), 4-5 in tf32 (polish)
    for (int it = 0; it < 4; it++) {
        bf16pinv_k<<<dim3(2, 2, BH), 256>>>(a2p, zin, t0p, SB, 0.f,  1.f, 1.f);
        bf16pinv_k<<<dim3(2, 2, BH), 256>>>(t0p, t0p, t1p, SB, 7.f, -1.f, 1.f);
        bf16pinv_k<<<dim3(2, 2, BH), 256>>>(t0p, t1p, t2p, SB, 15.f,-1.f, 1.f);
        bf16pinv_k<<<dim3(2, 2, BH), 256>>>(zin, t2p, zout,SB, 13.f,-1.f, 0.25f);
        float* tmp = zin; zin = zout; zout = tmp;
    }
    for (int it = 4; it < 6; it++) {
        tf32gemm_k<<<dim3(2, 2, BH), 256>>>(a2p, zin, t0p, 256, SB, 0.f,  1.f, 1.f);
        tf32gemm_k<<<dim3(2, 2, BH), 256>>>(t0p, t0p, t1p, 256, SB, 7.f, -1.f, 1.f);
        tf32gemm_k<<<dim3(2, 2, BH), 256>>>(t0p, t1p, t2p, 256, SB, 15.f,-1.f, 1.f);
        tf32gemm_k<<<dim3(2, 2, BH), 256>>>(zin, t2p, zout,256, SB, 13.f,-1.f, 0.25f);
        float* tmp = zin; zin = zout; zout = tmp;
    }
    // zin holds a2_inv (d_z0)

    cudaMemsetAsync(rsp, 0, (size_t)BH*ML*sizeof(float));
    cudaMemsetAsync(a3vp, 0, (size_t)BH*ML*DH*sizeof(float));
    a3_fused_k<<<dim3(8, 2, BH), 256, SM_FUSED_BYTES>>>();
    bgemm_epi<<<dim3(1, 4, BH), 256>>>(zin, a3vp, w2p, 256, 64, 256, 0.f, 1.f, 1.f, rsp);
    a1_fused_k<<<dim3(NP/128, BH), 256, SM_FUSED_BYTES>>>();

    conv_res_k<<<BB*NH*48, 256>>>(resw);
    bf16gemm_k<<<dim3(EMBD/128, NP/128, BB), 256>>>(
        attnp, outw, outb, hbuf, NP, EMBD, EMBD,
        (size_t)NP*256, (size_t)NT*EMBD, 2, 1);
}

extern "C" void kernel_launch(void* const* d_in, const int* in_sizes, int n_in,
                              void* d_out, int out_size)
{
    (void)in_sizes; (void)n_in; (void)out_size;
    const float* x_path = (const float*)d_in[0];
    const float* fc1_w  = (const float*)d_in[1];
    const float* fc1_b  = (const float*)d_in[2];
    const float* cls    = (const float*)d_in[3];
    const float* ln1g   = (const float*)d_in[4];
    const float* ln1b   = (const float*)d_in[5];
    const float* qkv1w  = (const float*)d_in[6];
    const float* out1w  = (const float*)d_in[7];
    const float* out1b  = (const float*)d_in[8];
    const float* res1w  = (const float*)d_in[9];
    const float* ln2g   = (const float*)d_in[10];
    const float* ln2b   = (const float*)d_in[11];
    const float* qkv2w  = (const float*)d_in[12];
    const float* out2w  = (const float*)d_in[13];
    const float* out2b  = (const float*)d_in[14];
    const float* res2w  = (const float*)d_in[15];
    const float* c7w    = (const float*)d_in[16];
    const float* c7b    = (const float*)d_in[17];
    const float* c5w    = (const float*)d_in[18];
    const float* c5b    = (const float*)d_in[19];
    const float* c3w    = (const float*)d_in[20];
    const float* c3b    = (const float*)d_in[21];
    const float* ng     = (const float*)d_in[22];
    const float* nb     = (const float*)d_in[23];
    const float* fc2w   = (const float*)d_in[24];
    const float* fc2b   = (const float*)d_in[25];
    float* out = (float*)d_out;

    static int cfg = 0;
    if (!cfg) {
        cudaFuncSetAttribute(a3_fused_k, cudaFuncAttributeMaxDynamicSharedMemorySize, SM_FUSED_BYTES);
        cudaFuncSetAttribute(a1_fused_k, cudaFuncAttributeMaxDynamicSharedMemorySize, SM_FUSED_BYTES);
        cudaFuncSetAttribute(ppeg3_k,    cudaFuncAttributeMaxDynamicSharedMemorySize, PP_SMEM_BYTES);
        cfg = 1;
    }

    float* hp  = symaddr(d_h);
    float* h2p = symaddr(d_h2);

    bf16gemm_k<<<dim3(EMBD/128, (N0 + 127)/128, BB), 256>>>(
        x_path, fc1_w, fc1_b, hp + EMBD, N0, EMBD, 1024,
        (size_t)N0*1024, (size_t)NT*EMBD, 1, 0);
    fill_cls_k<<<(BB*EMBD + 255)/256, 256>>>(cls);
    fill_wrap_k<<<(BB*ADDW*EMBD + 255)/256, 256>>>();
    wtrans_k<<<(49*EMBD + 255)/256, 256>>>(c7w, c5w, c3w);

    attn_layer(hp, ln1g, ln1b, qkv1w, out1w, out1b, res1w);

    ppeg3_k<<<dim3(16, HW, BB), 256, PP_SMEM_BYTES>>>(c7b, c5b, c3b);
    copy_cls_k<<<(BB*EMBD + 255)/256, 256>>>();

    attn_layer(h2p, ln2g, ln2b, qkv2w, out2w, out2b, res2w);

    head_k<<<BB, 256>>>(h2p, ng, nb, fc2w, fc2b, out);
}